// round 12
// baseline (speedup 1.0000x reference)
#include <cuda_runtime.h>
#include <cuda_bf16.h>
#include <math.h>
#include <stdint.h>

// ---------------- problem constants ----------------
#define CD     512
#define HF     38
#define WF     38
#define HW     1444
#define NOBJ   64
#define NREL   256
#define NIMG   2
#define NPIX   49
#define FC1K   25088
#define FCH    4096
#define MAPN   1536
#define OUTN   51
#define ROWS_PW 92416
#define PW_PART_BLOCKS 1024
#define PW_ROWS_PER 91

// ---------------- scratch ----------------
__device__ float g_dwf   [NOBJ*4608];
__device__ float g_pwf   [NOBJ*CD*CD];
__device__ float g_rf    [NIMG*CD*HW];
__device__ float g_dw    [NOBJ*CD*HW];            // [n][c][p]
__device__ float g_pw    [NOBJ*HW*CD];            // [n][p][d]
__device__ float g_dwinv [CD];
__device__ float g_dwsh  [CD];
__device__ float g_partS [PW_PART_BLOCKS*CD];
__device__ float g_partQ [PW_PART_BLOCKS*CD];
__device__ float g_pwinv [CD];
__device__ float g_pwsh  [CD];
__device__ float g_SO    [NREL*NPIX*1024];
__device__ float g_flat  [NREL*FC1K];
__device__ float g_h1    [NREL*FCH];
__device__ float g_rel   [NREL*FCH];
__device__ float g_sub   [NOBJ*1024];
__device__ float g_cat   [NREL*1024];
__device__ float g_lo    [NREL*MAPN];
__device__ float g_lr    [NREL*MAPN];
__device__ float g_t     [NREL*MAPN];
__device__ float g_part  [16*256*4096/2 + 8*256*4096/2]; // 8.4M floats (max use: 8x256x4096)

// ---------------- helpers ----------------
__device__ __forceinline__ uint32_t smem_u32(const void* p) {
    uint32_t a;
    asm("{ .reg .u64 t; cvta.to.shared.u64 t, %1; cvt.u32.u64 %0, t; }" : "=r"(a) : "l"(p));
    return a;
}
__device__ __forceinline__ unsigned packbf(__nv_bfloat16 a, __nv_bfloat16 b) {
    __nv_bfloat162 t = __halves2bfloat162(a, b);
    return *reinterpret_cast<unsigned*>(&t);
}
__device__ __forceinline__ void split2(float x, __nv_bfloat16& h, __nv_bfloat16& l) {
    h = __float2bfloat16(x);
    l = __float2bfloat16(x - __bfloat162float(h));
}
__device__ __forceinline__ void mma_bf16(float* c, const uint32_t* a, const uint32_t* b) {
    asm volatile(
        "mma.sync.aligned.m16n8k16.row.col.f32.bf16.bf16.f32 "
        "{%0,%1,%2,%3}, {%4,%5,%6,%7}, {%8,%9}, {%0,%1,%2,%3};\n"
        : "+f"(c[0]), "+f"(c[1]), "+f"(c[2]), "+f"(c[3])
        : "r"(a[0]), "r"(a[1]), "r"(a[2]), "r"(a[3]), "r"(b[0]), "r"(b[1]));
}
__device__ __forceinline__ void ldsm4(uint32_t& r0, uint32_t& r1, uint32_t& r2, uint32_t& r3, uint32_t addr) {
    asm volatile("ldmatrix.sync.aligned.m8n8.x4.shared.b16 {%0,%1,%2,%3}, [%4];"
                 : "=r"(r0), "=r"(r1), "=r"(r2), "=r"(r3) : "r"(addr));
}
__device__ __forceinline__ void ldsm4t(uint32_t& r0, uint32_t& r1, uint32_t& r2, uint32_t& r3, uint32_t addr) {
    asm volatile("ldmatrix.sync.aligned.m8n8.x4.trans.shared.b16 {%0,%1,%2,%3}, [%4];"
                 : "=r"(r0), "=r"(r1), "=r"(r2), "=r"(r3) : "r"(addr));
}

// smem (CTA tile 128m x 256n, K-chunk 32):
//  Ah @0 (8KB), Al @8K, Bh @16K (16KB), Bl @32K -> stage 48KB, double buffer 96KB.
// A m-major: 128 rows x 32 k (64B/row), chunk swz ^((row>>1)&3)
// A k-major: 32 k-rows x 256B (128 m), chunk swz ^(k&7)
// B m-major: 256 rows x 32 k (64B/row), chunk swz ^((row>>1)&3)
// B k-major: 32 k-rows x 512B (256 n), chunk swz ^(k&7)
#define APL    8192
#define SM_BH  16384
#define SM_BL  32768
#define STAGEB 49152
#define TG_SMEM 98304
__device__ __forceinline__ uint32_t offM(int row, int chunk) {
    return (uint32_t)(row * 64 + ((chunk ^ ((row >> 1) & 3)) << 4));
}
__device__ __forceinline__ uint32_t offKA(int k, int chunk) {
    return (uint32_t)(k * 256 + ((chunk ^ (k & 7)) << 4));
}
__device__ __forceinline__ uint32_t offKB(int k, int chunk) {
    return (uint32_t)(k * 512 + ((chunk ^ (k & 7)) << 4));
}

// =====================================================================
// mma.sync bf16x3 GEMM. Tile 128x256, 512 threads (16 warps, 4x4 grid,
// warp tile 32x64 -> 128B LDSM per MMA, crossbar ceiling ~80%).
// Double-buffered K=32 chunks, proven loop order: LDG -> COMPUTE -> STS -> bar.
// SRC_A/SRC_B: 0 = global m-major (X[row*ld+k]); 1 = global k-major (X[k*ld+row])
// BNA: a = a*inv[k]+sh[k].  BIAS 0/1(col)/2(row).  RELU.  OUTROI scatter.
// SPLITK: z = K-chunk of width kc (partials); else z = batch (sA,sB,sC).
// K (or kc) must be a multiple of 32.
// =====================================================================
template<int SRC_A, int SRC_B, bool BNA, int BIAS, bool RELU, bool OUTROI, bool SPLITK>
__global__ __launch_bounds__(512)
void tgemm(const float* __restrict__ A, const float* __restrict__ B,
           const float* __restrict__ bias, float* __restrict__ Cc,
           int M, int N, int K, int kc, int lda, int ldb, int ldc,
           long sA, long sB, long sC,
           const float* __restrict__ bninv, const float* __restrict__ bnsh)
{
    extern __shared__ char smc[];
    const uint32_t smem_base = smem_u32(smc);
    const int tid = threadIdx.x;
    const int lane = tid & 31, wid = tid >> 5;
    const int wm = wid >> 2, wn = wid & 3;     // 4x4 warps, warp tile 32x64
    const int g4 = lane >> 2, t4 = lane & 3;

    int k0;
    if (SPLITK) { k0 = blockIdx.z * kc; }
    else {
        A += (long)blockIdx.z * sA; B += (long)blockIdx.z * sB; Cc += (long)blockIdx.z * sC;
        k0 = 0;
    }
    const int m0 = blockIdx.y * 128;
    const int n0 = blockIdx.x * 256;
    const int nch = (SPLITK ? kc : K) / 32;

    const int ag = lane >> 3, ar = lane & 7;
    // non-trans fragment lane mapping (m-major planes)
    const int a_ml = ((ag & 1) << 3) + ar;
    const int a_kh = ag >> 1;
    const int b_nl = ((ag >> 1) << 3) + ar;
    const int b_kh = ag & 1;
    // trans fragment lane mapping (k-major planes)
    const int at_kr = ((ag >> 1) << 3) + ar;
    const int at_mc = ag & 1;
    const int bt_kr = ((ag & 1) << 3) + ar;
    const int bt_nc = ag >> 1;

    float acc[2][8][4];
#pragma unroll
    for (int a = 0; a < 2; a++)
#pragma unroll
        for (int b = 0; b < 8; b++)
#pragma unroll
            for (int c = 0; c < 4; c++) acc[a][b][c] = 0.f;

    float fa[8], fb[16];

    auto ldAg = [&](int kt) {
#pragma unroll
        for (int i = 0; i < 2; i++) {
            int e = tid + i * 512;
            if (SRC_A == 0) {
                int row = e >> 3, q = e & 7;
                int gm = m0 + row, gk = kt + q * 4;
                float4 v = make_float4(0.f, 0.f, 0.f, 0.f);
                if (gm < M) v = *reinterpret_cast<const float4*>(&A[(long)gm * lda + gk]);
                if (BNA) {
                    v.x = v.x * bninv[gk]   + bnsh[gk];
                    v.y = v.y * bninv[gk+1] + bnsh[gk+1];
                    v.z = v.z * bninv[gk+2] + bnsh[gk+2];
                    v.w = v.w * bninv[gk+3] + bnsh[gk+3];
                }
                fa[i*4+0]=v.x; fa[i*4+1]=v.y; fa[i*4+2]=v.z; fa[i*4+3]=v.w;
            } else {
                int k = e >> 5, mq = (e & 31) * 4;
                int gk = kt + k;
                float4 v = make_float4(0.f, 0.f, 0.f, 0.f);
                if (m0 + mq < M) v = *reinterpret_cast<const float4*>(&A[(long)gk * lda + m0 + mq]);
                if (BNA) {
                    float iv = bninv[gk], sv = bnsh[gk];
                    v.x = v.x*iv+sv; v.y = v.y*iv+sv; v.z = v.z*iv+sv; v.w = v.w*iv+sv;
                }
                fa[i*4+0]=v.x; fa[i*4+1]=v.y; fa[i*4+2]=v.z; fa[i*4+3]=v.w;
            }
        }
    };
    auto ldBg = [&](int kt) {
#pragma unroll
        for (int i = 0; i < 4; i++) {
            int e = tid + i * 512;
            if (SRC_B == 0) {
                int row = e >> 3, q = e & 7;
                int gn = n0 + row, gk = kt + q * 4;
                float4 v = make_float4(0.f, 0.f, 0.f, 0.f);
                if (gn < N) v = *reinterpret_cast<const float4*>(&B[(long)gn * ldb + gk]);
                fb[i*4+0]=v.x; fb[i*4+1]=v.y; fb[i*4+2]=v.z; fb[i*4+3]=v.w;
            } else {
                int k = e >> 6, nq = (e & 63) * 4;
                int gk = kt + k, gn = n0 + nq;
                float4 v;
                if (gn + 3 < N) v = *reinterpret_cast<const float4*>(&B[(long)gk * ldb + gn]);
                else {
                    v.x = (gn   < N) ? B[(long)gk * ldb + gn]   : 0.f;
                    v.y = (gn+1 < N) ? B[(long)gk * ldb + gn+1] : 0.f;
                    v.z = (gn+2 < N) ? B[(long)gk * ldb + gn+2] : 0.f;
                    v.w = (gn+3 < N) ? B[(long)gk * ldb + gn+3] : 0.f;
                }
                fb[i*4+0]=v.x; fb[i*4+1]=v.y; fb[i*4+2]=v.z; fb[i*4+3]=v.w;
            }
        }
    };
    auto stA = [&](int st) {
        char* hb = smc + st * STAGEB;
        char* lb = hb + APL;
#pragma unroll
        for (int i = 0; i < 2; i++) {
            int e = tid + i * 512;
            __nv_bfloat16 h[4], l[4];
#pragma unroll
            for (int j = 0; j < 4; j++) split2(fa[i*4+j], h[j], l[j]);
            uint32_t off;
            if (SRC_A == 0) {
                int row = e >> 3, q = e & 7;
                off = offM(row, q >> 1) + (uint32_t)((q & 1) << 3);
            } else {
                int k = e >> 5, mq = (e & 31) * 4;
                off = offKA(k, mq >> 3) + (uint32_t)((mq & 7) << 1);
            }
            *reinterpret_cast<uint2*>(hb + off) = make_uint2(packbf(h[0],h[1]), packbf(h[2],h[3]));
            *reinterpret_cast<uint2*>(lb + off) = make_uint2(packbf(l[0],l[1]), packbf(l[2],l[3]));
        }
    };
    auto stB = [&](int st) {
        char* hb = smc + st * STAGEB + SM_BH;
        char* lb = smc + st * STAGEB + SM_BL;
#pragma unroll
        for (int i = 0; i < 4; i++) {
            int e = tid + i * 512;
            __nv_bfloat16 h[4], l[4];
#pragma unroll
            for (int j = 0; j < 4; j++) split2(fb[i*4+j], h[j], l[j]);
            uint32_t off;
            if (SRC_B == 0) {
                int row = e >> 3, q = e & 7;
                off = offM(row, q >> 1) + (uint32_t)((q & 1) << 3);
            } else {
                int k = e >> 6, nq = (e & 63) * 4;
                off = offKB(k, nq >> 3) + (uint32_t)((nq & 7) << 1);
            }
            *reinterpret_cast<uint2*>(hb + off) = make_uint2(packbf(h[0],h[1]), packbf(h[2],h[3]));
            *reinterpret_cast<uint2*>(lb + off) = make_uint2(packbf(l[0],l[1]), packbf(l[2],l[3]));
        }
    };

    ldAg(k0); ldBg(k0);
    stA(0); stB(0);
    __syncthreads();

    int bb = 0;
    for (int c = 0; c < nch; c++) {
        bool nxt = (c + 1) < nch;
        if (nxt) { ldAg(k0 + (c + 1) * 32); ldBg(k0 + (c + 1) * 32); }

        uint32_t sb = smem_base + bb * STAGEB;
#pragma unroll
        for (int ks = 0; ks < 2; ks++) {
            uint32_t bhF[4][4], blF[4][4];
#pragma unroll
            for (int nh = 0; nh < 4; nh++) {
                if (SRC_B == 0) {
                    int n = wn * 64 + nh * 16 + b_nl;
                    uint32_t off = offM(n, ks * 2 + b_kh);
                    ldsm4(bhF[nh][0], bhF[nh][1], bhF[nh][2], bhF[nh][3], sb + SM_BH + off);
                    ldsm4(blF[nh][0], blF[nh][1], blF[nh][2], blF[nh][3], sb + SM_BL + off);
                } else {
                    int kr = ks * 16 + bt_kr;
                    int nc = wn * 8 + nh * 2 + bt_nc;
                    uint32_t off = offKB(kr, nc);
                    ldsm4t(bhF[nh][0], bhF[nh][1], bhF[nh][2], bhF[nh][3], sb + SM_BH + off);
                    ldsm4t(blF[nh][0], blF[nh][1], blF[nh][2], blF[nh][3], sb + SM_BL + off);
                }
            }
#pragma unroll
            for (int mt = 0; mt < 2; mt++) {
                uint32_t ah[4], al[4];
                if (SRC_A == 0) {
                    int m = wm * 32 + mt * 16 + a_ml;
                    uint32_t off = offM(m, ks * 2 + a_kh);
                    ldsm4(ah[0], ah[1], ah[2], ah[3], sb + off);
                    ldsm4(al[0], al[1], al[2], al[3], sb + APL + off);
                } else {
                    int kr = ks * 16 + at_kr;
                    int mc = wm * 4 + mt * 2 + at_mc;
                    uint32_t off = offKA(kr, mc);
                    ldsm4t(ah[0], ah[1], ah[2], ah[3], sb + off);
                    ldsm4t(al[0], al[1], al[2], al[3], sb + APL + off);
                }
#pragma unroll
                for (int nt = 0; nt < 8; nt++) {
                    const uint32_t* bh2 = &bhF[nt >> 1][(nt & 1) * 2];
                    const uint32_t* bl2 = &blF[nt >> 1][(nt & 1) * 2];
                    mma_bf16(acc[mt][nt], ah, bh2);
                    mma_bf16(acc[mt][nt], ah, bl2);
                    mma_bf16(acc[mt][nt], al, bh2);
                }
            }
        }
        if (!nxt) break;
        int nb = bb ^ 1;
        stA(nb); stB(nb);
        __syncthreads();
        bb = nb;
    }

    // ---- epilogue ----
#pragma unroll
    for (int mt = 0; mt < 2; mt++) {
#pragma unroll
        for (int nt = 0; nt < 8; nt++) {
#pragma unroll
            for (int e = 0; e < 4; e++) {
                int gm = m0 + wm * 32 + mt * 16 + g4 + ((e >= 2) ? 8 : 0);
                int gn = n0 + wn * 64 + nt * 8 + 2 * t4 + (e & 1);
                if (gm >= M || gn >= N) continue;
                float v = acc[mt][nt][e];
                if (SPLITK) {
                    Cc[((long)blockIdx.z * M + gm) * (long)N + gn] = v;
                } else {
                    if (BIAS == 1) v += bias[gn];
                    if (BIAS == 2) v += bias[gm];
                    if (RELU) v = fmaxf(v, 0.f);
                    long off;
                    if (OUTROI) { int r = gm / 49; int p = gm - r * 49; off = (long)r * FC1K + (long)gn * 49 + p; }
                    else        { off = (long)gm * ldc + gn; }
                    Cc[off] = v;
                }
            }
        }
    }
}

// ---------------- fp32 tiled SGEMM (comp only, split-K) ----------------
template<bool SPLITK>
__global__ __launch_bounds__(256)
void gemm_k(const float* __restrict__ A, const float* __restrict__ B,
            float* __restrict__ Cc, int M, int N, int K, int kc, int lda, int ldb)
{
    __shared__ float As[2][16][128];
    __shared__ float Bs[2][16][128];
    int k0 = blockIdx.z * kc, kend = k0 + kc;
    const int m0 = blockIdx.y * 128;
    const int n0 = blockIdx.x * 128;
    const int tid = threadIdx.x;
    const int tx = tid & 15;
    const int ty = tid >> 4;

    float acc[8][8];
#pragma unroll
    for (int i = 0; i < 8; i++)
#pragma unroll
        for (int j = 0; j < 8; j++) acc[i][j] = 0.f;

#pragma unroll
    for (int i = 0; i < 8; i++) {
        int idx = tid + i * 256;
        int m = idx >> 4, k = idx & 15;
        int gm = m0 + m, gk = k0 + k;
        As[0][k][m] = (gm < M) ? A[(long)gm * lda + gk] : 0.f;
    }
#pragma unroll
    for (int i = 0; i < 8; i++) {
        int idx = tid + i * 256;
        int k = idx >> 7, n = idx & 127;
        int gn = n0 + n, gk = k0 + k;
        Bs[0][k][n] = (gn < N) ? B[(long)gk * ldb + gn] : 0.f;
    }
    __syncthreads();

    int bb = 0;
    for (int kt = k0 + 16; ; kt += 16) {
        bool nxt = kt < kend;
        float ra[8], rb[8];
        if (nxt) {
#pragma unroll
            for (int i = 0; i < 8; i++) {
                int idx = tid + i * 256;
                int m = idx >> 4, k = idx & 15;
                int gm = m0 + m, gk = kt + k;
                ra[i] = (gm < M) ? A[(long)gm * lda + gk] : 0.f;
            }
#pragma unroll
            for (int i = 0; i < 8; i++) {
                int idx = tid + i * 256;
                int k = idx >> 7, n = idx & 127;
                int gn = n0 + n, gk = kt + k;
                rb[i] = (gn < N) ? B[(long)gk * ldb + gn] : 0.f;
            }
        }
#pragma unroll
        for (int k = 0; k < 16; k++) {
            float4 a0 = *reinterpret_cast<const float4*>(&As[bb][k][ty * 4]);
            float4 a1 = *reinterpret_cast<const float4*>(&As[bb][k][64 + ty * 4]);
            float4 b0 = *reinterpret_cast<const float4*>(&Bs[bb][k][tx * 4]);
            float4 b1 = *reinterpret_cast<const float4*>(&Bs[bb][k][64 + tx * 4]);
            float a[8] = {a0.x,a0.y,a0.z,a0.w,a1.x,a1.y,a1.z,a1.w};
            float b[8] = {b0.x,b0.y,b0.z,b0.w,b1.x,b1.y,b1.z,b1.w};
#pragma unroll
            for (int i = 0; i < 8; i++)
#pragma unroll
                for (int j = 0; j < 8; j++)
                    acc[i][j] += a[i] * b[j];
        }
        if (!nxt) break;
        int nb = bb ^ 1;
#pragma unroll
        for (int i = 0; i < 8; i++) {
            int idx = tid + i * 256;
            int m = idx >> 4, k = idx & 15;
            As[nb][k][m] = ra[i];
        }
#pragma unroll
        for (int i = 0; i < 8; i++) {
            int idx = tid + i * 256;
            int k = idx >> 7, n = idx & 127;
            Bs[nb][k][n] = rb[i];
        }
        __syncthreads();
        bb = nb;
    }

#pragma unroll
    for (int i = 0; i < 8; i++) {
        int gm = m0 + ((i < 4) ? ty * 4 + i : 64 + ty * 4 + (i - 4));
        if (gm >= M) continue;
#pragma unroll
        for (int j = 0; j < 8; j++) {
            int gn = n0 + ((j < 4) ? tx * 4 + j : 64 + tx * 4 + (j - 4));
            if (gn >= N) continue;
            Cc[((long)blockIdx.z * M + gm) * (long)N + gn] = acc[i][j];
        }
    }
}

// ---------------- skinny SGEMM: 64(M) x 128(N) ----------------
template<bool VECB, bool DIRECT, bool RELU>
__global__ __launch_bounds__(256)
void gemm_sk(const float* __restrict__ A, const float* __restrict__ B,
             const float* __restrict__ bias, float* __restrict__ Cc,
             int M, int N, int kc, int lda, int ldb, int ldc)
{
    __shared__ float As[2][16][64];
    __shared__ float Bs[2][16][128];
    const int m0 = blockIdx.y * 64, n0 = blockIdx.x * 128;
    const int k0 = blockIdx.z * kc;
    const int tid = threadIdx.x, tx = tid & 15, ty = tid >> 4;
    const int am = tid >> 2, akq = (tid & 3) * 4;
    const int bk = tid >> 4, bn = (tid & 15) * 8;

    float acc[4][8];
#pragma unroll
    for (int i = 0; i < 4; i++)
#pragma unroll
        for (int j = 0; j < 8; j++) acc[i][j] = 0.f;

    {
        float4 v = *reinterpret_cast<const float4*>(&A[(long)(m0 + am) * lda + k0 + akq]);
        As[0][akq + 0][am] = v.x; As[0][akq + 1][am] = v.y;
        As[0][akq + 2][am] = v.z; As[0][akq + 3][am] = v.w;
        if (VECB) {
            float4 b0v = *reinterpret_cast<const float4*>(&B[(long)(k0 + bk) * ldb + n0 + bn]);
            float4 b1v = *reinterpret_cast<const float4*>(&B[(long)(k0 + bk) * ldb + n0 + bn + 4]);
            *reinterpret_cast<float4*>(&Bs[0][bk][bn]) = b0v;
            *reinterpret_cast<float4*>(&Bs[0][bk][bn + 4]) = b1v;
        } else {
#pragma unroll
            for (int j = 0; j < 8; j++) {
                int gn = n0 + bn + j;
                Bs[0][bk][bn + j] = (gn < N) ? B[(long)(k0 + bk) * ldb + gn] : 0.f;
            }
        }
    }
    __syncthreads();

    int bb = 0;
    for (int kt = k0 + 16; ; kt += 16) {
        bool nxt = kt < k0 + kc;
        float4 va, vb0, vb1; float sb[8];
        if (nxt) {
            va = *reinterpret_cast<const float4*>(&A[(long)(m0 + am) * lda + kt + akq]);
            if (VECB) {
                vb0 = *reinterpret_cast<const float4*>(&B[(long)(kt + bk) * ldb + n0 + bn]);
                vb1 = *reinterpret_cast<const float4*>(&B[(long)(kt + bk) * ldb + n0 + bn + 4]);
            } else {
#pragma unroll
                for (int j = 0; j < 8; j++) {
                    int gn = n0 + bn + j;
                    sb[j] = (gn < N) ? B[(long)(kt + bk) * ldb + gn] : 0.f;
                }
            }
        }
#pragma unroll
        for (int k = 0; k < 16; k++) {
            float4 a0 = *reinterpret_cast<const float4*>(&As[bb][k][ty * 4]);
            float4 b0 = *reinterpret_cast<const float4*>(&Bs[bb][k][tx * 4]);
            float4 b1 = *reinterpret_cast<const float4*>(&Bs[bb][k][64 + tx * 4]);
            float a[4] = {a0.x,a0.y,a0.z,a0.w};
            float b[8] = {b0.x,b0.y,b0.z,b0.w,b1.x,b1.y,b1.z,b1.w};
#pragma unroll
            for (int i = 0; i < 4; i++)
#pragma unroll
                for (int j = 0; j < 8; j++)
                    acc[i][j] += a[i] * b[j];
        }
        if (!nxt) break;
        int nb = bb ^ 1;
        As[nb][akq + 0][am] = va.x; As[nb][akq + 1][am] = va.y;
        As[nb][akq + 2][am] = va.z; As[nb][akq + 3][am] = va.w;
        if (VECB) {
            *reinterpret_cast<float4*>(&Bs[nb][bk][bn]) = vb0;
            *reinterpret_cast<float4*>(&Bs[nb][bk][bn + 4]) = vb1;
        } else {
#pragma unroll
            for (int j = 0; j < 8; j++) Bs[nb][bk][bn + j] = sb[j];
        }
        __syncthreads();
        bb = nb;
    }

#pragma unroll
    for (int i = 0; i < 4; i++) {
        int gm = m0 + ty * 4 + i;
#pragma unroll
        for (int j = 0; j < 8; j++) {
            int gn = n0 + ((j < 4) ? tx * 4 + j : 64 + tx * 4 + (j - 4));
            if (gn >= N) continue;
            float v = acc[i][j];
            if (DIRECT) {
                v += bias[gn];
                if (RELU) v = fmaxf(v, 0.f);
                Cc[(long)gm * ldc + gn] = v;
            } else {
                Cc[((long)blockIdx.z * M + gm) * (long)N + gn] = v;
            }
        }
    }
}

// ---------------- split-K reduce ----------------
__global__ void reduce_k(const float* __restrict__ part, const float* __restrict__ bias,
                         float* __restrict__ C, int M, int N, int S, int ldc, int relu)
{
    int idx = blockIdx.x * 256 + threadIdx.x;
    if (idx >= M * N) return;
    int m = idx / N, n = idx - m * N;
    float v = 0.f;
    for (int s = 0; s < S; s++) v += part[(long)s * M * N + idx];
    v += bias[n];
    if (relu) v = fmaxf(v, 0.f);
    C[(long)m * ldc + n] = v;
}

// ---------------- depthwise 3x3 conv (padded smem, no bounds checks) ----------------
__global__ void dwconv_k(const float* __restrict__ rf, const float* __restrict__ dwf,
                         const int* __restrict__ im_inds, float* __restrict__ dw)
{
    int n = blockIdx.x, c = blockIdx.y;
    __shared__ float plane[40 * 40];
    __shared__ float f[9];
    int im = im_inds[n];
    const float* src = rf + ((long)im * CD + c) * HW;
    for (int i = threadIdx.x; i < 1600; i += 256) plane[i] = 0.f;
    if (threadIdx.x < 9) f[threadIdx.x] = dwf[((long)n * CD + c) * 9 + threadIdx.x];
    __syncthreads();
    for (int i = threadIdx.x; i < HW; i += 256) {
        int y = i / WF, x = i - y * WF;
        plane[(y + 1) * 40 + x + 1] = src[i];
    }
    __syncthreads();
    float* dst = dw + ((long)n * CD + c) * HW;
    for (int p = threadIdx.x; p < HW; p += 256) {
        int y = p / WF, x = p - y * WF;
        const float* b = &plane[y * 40 + x];
        float s = b[0]  * f[0] + b[1]  * f[1] + b[2]  * f[2]
                + b[40] * f[3] + b[41] * f[4] + b[42] * f[5]
                + b[80] * f[6] + b[81] * f[7] + b[82] * f[8];
        dst[p] = s;
    }
}

// ---------------- dw BN stats ----------------
__global__ void dwstats_k(const float* __restrict__ dw, const float* __restrict__ scale,
                          const float* __restrict__ bias, float* __restrict__ inv,
                          float* __restrict__ sh)
{
    int c = blockIdx.x;
    double s = 0.0, q = 0.0;
    for (int n = 0; n < NOBJ; n++) {
        const float* row = dw + ((long)n * CD + c) * HW;
        for (int p = threadIdx.x; p < HW; p += 256) {
            float v = row[p];
            s += v; q += (double)v * v;
        }
    }
    __shared__ double rs[256], rq[256];
    rs[threadIdx.x] = s; rq[threadIdx.x] = q;
    __syncthreads();
    for (int o = 128; o > 0; o >>= 1) {
        if (threadIdx.x < o) { rs[threadIdx.x] += rs[threadIdx.x + o]; rq[threadIdx.x] += rq[threadIdx.x + o]; }
        __syncthreads();
    }
    if (threadIdx.x == 0) {
        double cnt = (double)ROWS_PW;
        double m = rs[0] / cnt;
        double var = rq[0] / cnt - m * m;
        float iv = scale[c] * (float)(1.0 / sqrt(var + 1e-5));
        inv[c] = iv;
        sh[c]  = bias[c] - (float)m * iv;
    }
}

// ---------------- pw BN stats ----------------
__global__ void pwpart_k(const float* __restrict__ pw, float* __restrict__ pS, float* __restrict__ pQ)
{
    int blk = blockIdx.x;
    int t = threadIdx.x;
    float s0 = 0, q0 = 0, s1 = 0, q1 = 0;
    int r0 = blk * PW_ROWS_PER;
    int r1 = min(ROWS_PW, r0 + PW_ROWS_PER);
    for (int r = r0; r < r1; r++) {
        const float* row = pw + (long)r * CD;
        float v0 = row[t], v1 = row[t + 256];
        s0 += v0; q0 += v0 * v0;
        s1 += v1; q1 += v1 * v1;
    }
    pS[(long)blk * CD + t] = s0;       pS[(long)blk * CD + t + 256] = s1;
    pQ[(long)blk * CD + t] = q0;       pQ[(long)blk * CD + t + 256] = q1;
}

__global__ void pwfin_k(const float* __restrict__ pS, const float* __restrict__ pQ,
                        const float* __restrict__ scale, const float* __restrict__ bias,
                        float* __restrict__ inv, float* __restrict__ sh)
{
    int d = blockIdx.x;
    double s = 0.0, q = 0.0;
    for (int b = threadIdx.x; b < PW_PART_BLOCKS; b += 256) {
        s += pS[(long)b * CD + d];
        q += pQ[(long)b * CD + d];
    }
    __shared__ double rs[256], rq[256];
    rs[threadIdx.x] = s; rq[threadIdx.x] = q;
    __syncthreads();
    for (int o = 128; o > 0; o >>= 1) {
        if (threadIdx.x < o) { rs[threadIdx.x] += rs[threadIdx.x + o]; rq[threadIdx.x] += rq[threadIdx.x + o]; }
        __syncthreads();
    }
    if (threadIdx.x == 0) {
        double cnt = (double)ROWS_PW;
        double m = rs[0] / cnt;
        double var = rq[0] / cnt - m * m;
        float iv = scale[d] * (float)(1.0 / sqrt(var + 1e-5));
        inv[d] = iv;
        sh[d]  = bias[d] - (float)m * iv;
    }
}

// ---------------- ROI-align 7x7 with fused BN+ReLU ----------------
__global__ void roi_k(const float* __restrict__ pw, const float* __restrict__ boxes,
                      const int* __restrict__ rel_inds, const float* __restrict__ inv,
                      const float* __restrict__ sh, float* __restrict__ SO)
{
    int b = blockIdx.x;
    int r = b >> 1, role = b & 1;
    int obj = rel_inds[r * 2 + role];

    __shared__ int yi0[7], yi1[7], xi0[7], xi1[7];
    __shared__ float wy[7], wx[7];
    if (threadIdx.x < 14) {
        int i = threadIdx.x % 7;
        bool isY = threadIdx.x < 7;
        float lo = boxes[obj * 4 + (isY ? 1 : 0)] * (1.0f / 16.0f);
        float hi = boxes[obj * 4 + (isY ? 3 : 2)] * (1.0f / 16.0f);
        float g = ((float)i + 0.5f) / 7.0f;
        float v = lo + (hi - lo) * g;
        float f0 = floorf(v);
        float w = v - f0;
        int i0 = min(max((int)f0, 0), HF - 1);
        int i1 = min(i0 + 1, HF - 1);
        if (isY) { yi0[i] = i0; yi1[i] = i1; wy[i] = w; }
        else     { xi0[i] = i0; xi1[i] = i1; wx[i] = w; }
    }
    __syncthreads();

    const float* base = pw + (long)obj * HW * CD;
    float* dst = SO + (long)r * NPIX * 1024 + role * CD;

    for (int e = threadIdx.x; e < NPIX * CD; e += 256) {
        int pix = e >> 9;
        int c = e & 511;
        int iy = pix / 7, ix = pix - iy * 7;
        int y0 = yi0[iy], y1 = yi1[iy], x0 = xi0[ix], x1 = xi1[ix];
        float fy = wy[iy], fx = wx[ix];
        float ivv = inv[c], shv = sh[c];
        float v00 = fmaxf(base[(long)(y0 * WF + x0) * CD + c] * ivv + shv, 0.f);
        float v01 = fmaxf(base[(long)(y0 * WF + x1) * CD + c] * ivv + shv, 0.f);
        float v10 = fmaxf(base[(long)(y1 * WF + x0) * CD + c] * ivv + shv, 0.f);
        float v11 = fmaxf(base[(long)(y1 * WF + x1) * CD + c] * ivv + shv, 0.f);
        float out = v00 * (1.f - fy) * (1.f - fx) + v01 * (1.f - fy) * fx
                  + v10 * fy * (1.f - fx)         + v11 * fy * fx;
        dst[(long)pix * 1024 + c] = out;
    }
}

// ---------------- concat / triple ----------------
__global__ void cat_k(const float* __restrict__ sub, const int* __restrict__ rel_inds,
                      float* __restrict__ cat)
{
    int idx = blockIdx.x * 256 + threadIdx.x;
    if (idx >= NREL * 1024) return;
    int r = idx >> 10;
    int c = idx & 1023;
    int obj = rel_inds[r * 2 + (c < 512 ? 0 : 1)];
    cat[idx] = sub[(long)obj * 1024 + c];
}

__global__ void triple_k(const float* __restrict__ lo, const float* __restrict__ lr,
                         float* __restrict__ t)
{
    int idx = blockIdx.x * 256 + threadIdx.x;
    if (idx >= NREL * MAPN) return;
    float a = lo[idx], b = lr[idx];
    float d = a - b;
    t[idx] = fmaxf(a + b, 0.f) - d * d;
}

// ---------------- host ----------------
extern "C" void kernel_launch(void* const* d_in, const int* in_sizes, int n_in,
                              void* d_out, int out_size)
{
    (void)in_sizes; (void)n_in; (void)out_size;
    const float* fmaps     = (const float*)d_in[0];
    const float* boxes     = (const float*)d_in[1];
    const float* rof       = (const float*)d_in[2];
    const float* reduce_w  = (const float*)d_in[3];
    const float* reduce_b  = (const float*)d_in[4];
    const float* dw_gen_w  = (const float*)d_in[5];
    const float* dw_gen_b  = (const float*)d_in[6];
    const float* pw_gen_w  = (const float*)d_in[7];
    const float* pw_gen_b  = (const float*)d_in[8];
    const float* dw_bns    = (const float*)d_in[9];
    const float* dw_bnb    = (const float*)d_in[10];
    const float* pw_bns    = (const float*)d_in[11];
    const float* pw_bnb    = (const float*)d_in[12];
    const float* recover_w = (const float*)d_in[13];
    const float* recover_b = (const float*)d_in[14];
    const float* fc1_w     = (const float*)d_in[15];
    const float* fc1_b     = (const float*)d_in[16];
    const float* fc2_w     = (const float*)d_in[17];
    const float* fc2_b     = (const float*)d_in[18];
    const float* post_w    = (const float*)d_in[19];
    const float* post_b    = (const float*)d_in[20];
    const float* map_w     = (const float*)d_in[21];
    const float* map_b     = (const float*)d_in[22];
    const float* rr_w      = (const float*)d_in[23];
    const float* rr_b      = (const float*)d_in[24];
    const float* comp_w    = (const float*)d_in[25];
    const float* comp_b    = (const float*)d_in[26];
    const int*   im_inds   = (const int*)d_in[27];
    const int*   rel_inds  = (const int*)d_in[28];
    float* out = (float*)d_out;

    float *p_dwf, *p_pwf, *p_rf, *p_dw, *p_pw, *p_dwinv, *p_dwsh, *p_pS, *p_pQ,
          *p_pwinv, *p_pwsh, *p_SO, *p_flat, *p_h1, *p_rel, *p_sub, *p_cat,
          *p_lo, *p_lr, *p_t, *p_part;
    cudaGetSymbolAddress((void**)&p_dwf, g_dwf);
    cudaGetSymbolAddress((void**)&p_pwf, g_pwf);
    cudaGetSymbolAddress((void**)&p_rf, g_rf);
    cudaGetSymbolAddress((void**)&p_dw, g_dw);
    cudaGetSymbolAddress((void**)&p_pw, g_pw);
    cudaGetSymbolAddress((void**)&p_dwinv, g_dwinv);
    cudaGetSymbolAddress((void**)&p_dwsh, g_dwsh);
    cudaGetSymbolAddress((void**)&p_pS, g_partS);
    cudaGetSymbolAddress((void**)&p_pQ, g_partQ);
    cudaGetSymbolAddress((void**)&p_pwinv, g_pwinv);
    cudaGetSymbolAddress((void**)&p_pwsh, g_pwsh);
    cudaGetSymbolAddress((void**)&p_SO, g_SO);
    cudaGetSymbolAddress((void**)&p_flat, g_flat);
    cudaGetSymbolAddress((void**)&p_h1, g_h1);
    cudaGetSymbolAddress((void**)&p_rel, g_rel);
    cudaGetSymbolAddress((void**)&p_sub, g_sub);
    cudaGetSymbolAddress((void**)&p_cat, g_cat);
    cudaGetSymbolAddress((void**)&p_lo, g_lo);
    cudaGetSymbolAddress((void**)&p_lr, g_lr);
    cudaGetSymbolAddress((void**)&p_t, g_t);
    cudaGetSymbolAddress((void**)&p_part, g_part);

    auto T_pwf = tgemm<0,1,false,1,false,false,false>;
    auto T_rf  = tgemm<1,1,false,2,true ,false,false>;
    auto T_pwe = tgemm<1,0,true ,0,false,false,false>;
    auto T_rec = tgemm<0,1,false,1,false,true ,false>;
    auto T_sk  = tgemm<0,1,false,0,false,false,true >;
    cudaFuncSetAttribute(T_pwf, cudaFuncAttributeMaxDynamicSharedMemorySize, TG_SMEM);
    cudaFuncSetAttribute(T_rf , cudaFuncAttributeMaxDynamicSharedMemorySize, TG_SMEM);
    cudaFuncSetAttribute(T_pwe, cudaFuncAttributeMaxDynamicSharedMemorySize, TG_SMEM);
    cudaFuncSetAttribute(T_rec, cudaFuncAttributeMaxDynamicSharedMemorySize, TG_SMEM);
    cudaFuncSetAttribute(T_sk , cudaFuncAttributeMaxDynamicSharedMemorySize, TG_SMEM);

    // 1) dw_f = rof @ dw_gen_w + b (fp32 skinny split-K)
    gemm_sk<true,false,false><<<dim3(36,1,4),256>>>(
        rof, dw_gen_w, nullptr, p_part, 64,4608,128, 512,4608,0);
    reduce_k<<<(64*4608+255)/256,256>>>(p_part, dw_gen_b, p_dwf, 64,4608,4,4608,0);

    // 2) pw_f = rof @ pw_gen_w + b  (N tiles of 256)
    T_pwf<<<dim3(1024,1,1),512,TG_SMEM>>>(
        rof, pw_gen_w, pw_gen_b, p_pwf, 64,262144,512,0, 512,262144,262144,
        0,0,0, nullptr,nullptr);

    // 3) rf[b][o][p] = relu(W^T fm + b)
    T_rf<<<dim3(6,4,2),512,TG_SMEM>>>(
        reduce_w, fmaps, reduce_b, p_rf, CD,HW,CD,0, CD,HW,HW,
        0, (long)CD*HW, (long)CD*HW, nullptr,nullptr);

    // 4) depthwise conv
    dwconv_k<<<dim3(NOBJ,CD),256>>>(p_rf, p_dwf, im_inds, p_dw);

    // 5) dw BN params
    dwstats_k<<<CD,256>>>(p_dw, dw_bns, dw_bnb, p_dwinv, p_dwsh);

    // 6) pw[n][p][d] = bn(dw^T) @ pwf^T   (batch 64)
    T_pwe<<<dim3(2,12,64),512,TG_SMEM>>>(
        p_dw, p_pwf, nullptr, p_pw, HW,CD,CD,0, HW,CD,CD,
        (long)CD*HW, (long)CD*CD, (long)HW*CD, p_dwinv, p_dwsh);

    // 7) pw BN stats
    pwpart_k<<<PW_PART_BLOCKS,256>>>(p_pw, p_pS, p_pQ);
    pwfin_k<<<CD,256>>>(p_pS, p_pQ, pw_bns, pw_bnb, p_pwinv, p_pwsh);

    // 8) ROI align
    roi_k<<<NREL*2,256>>>(p_pw, boxes, rel_inds, p_pwinv, p_pwsh, p_SO);

    // 9) rec = SO @ recover_w + b, ROI scatter
    T_rec<<<dim3(2,98,1),512,TG_SMEM>>>(
        p_SO, recover_w, recover_b, p_flat, NREL*NPIX,CD,1024,0, 1024,CD,0,
        0,0,0, nullptr,nullptr);

    // 10) fc1 (split-K S=8, kc=3136)
    T_sk<<<dim3(16,2,8),512,TG_SMEM>>>(
        p_flat, fc1_w, nullptr, p_part, NREL,FCH,FC1K,3136, FC1K,FCH,0,
        0,0,0, nullptr,nullptr);
    reduce_k<<<(NREL*FCH+255)/256,256>>>(p_part, fc1_b, p_h1, NREL,FCH,8,FCH,1);

    // 11) fc2 (split-K S=8, kc=512)
    T_sk<<<dim3(16,2,8),512,TG_SMEM>>>(
        p_h1, fc2_w, nullptr, p_part, NREL,FCH,FCH,512, FCH,FCH,0,
        0,0,0, nullptr,nullptr);
    reduce_k<<<(NREL*FCH+255)/256,256>>>(p_part, fc2_b, p_rel, NREL,FCH,8,FCH,0);

    // 12) subobj (fp32 skinny)
    gemm_sk<true,false,false><<<dim3(8,1,8),256>>>(
        rof, post_w, nullptr, p_part, 64,1024,64, 512,1024,0);
    reduce_k<<<(64*1024+255)/256,256>>>(p_part, post_b, p_sub, 64,1024,8,1024,0);

    // 13) cat
    cat_k<<<(NREL*1024+255)/256,256>>>(p_sub, rel_inds, p_cat);

    // 14) last_obj (split-K S=8, kc=128)
    T_sk<<<dim3(6,2,8),512,TG_SMEM>>>(
        p_cat, map_w, nullptr, p_part, NREL,MAPN,1024,128, 1024,MAPN,0,
        0,0,0, nullptr,nullptr);
    reduce_k<<<(NREL*MAPN+255)/256,256>>>(p_part, map_b, p_lo, NREL,MAPN,8,MAPN,0);

    // 15) last_rel (split-K S=16, kc=256)
    T_sk<<<dim3(6,2,16),512,TG_SMEM>>>(
        p_rel, rr_w, nullptr, p_part, NREL,MAPN,FCH,256, FCH,MAPN,0,
        0,0,0, nullptr,nullptr);
    reduce_k<<<(NREL*MAPN+255)/256,256>>>(p_part, rr_b, p_lr, NREL,MAPN,16,MAPN,0);

    // 16) triple
    triple_k<<<(NREL*MAPN+255)/256,256>>>(p_lo, p_lr, p_t);

    // 17) comp (fp32, N=51, split-K S=8)
    gemm_k<true><<<dim3(1,2,8),256>>>(
        p_t, comp_w, p_part, NREL,OUTN,MAPN,192, MAPN,OUTN);
    reduce_k<<<(NREL*OUTN+255)/256,256>>>(p_part, comp_b, out, NREL,OUTN,8,OUTN,0);
}

// round 13
// speedup vs baseline: 1.1794x; 1.1794x over previous
#include <cuda_runtime.h>
#include <cuda_bf16.h>
#include <math.h>
#include <stdint.h>

// ---------------- problem constants ----------------
#define CD     512
#define HF     38
#define WF     38
#define HW     1444
#define NOBJ   64
#define NREL   256
#define NIMG   2
#define NPIX   49
#define FC1K   25088
#define FCH    4096
#define MAPN   1536
#define OUTN   51
#define ROWS_PW 92416
#define PW_PART_BLOCKS 1024
#define PW_ROWS_PER 91

// ---------------- scratch ----------------
__device__ float g_dwf   [NOBJ*4608];
__device__ float g_pwf   [NOBJ*CD*CD];
__device__ float g_rf    [NIMG*CD*HW];
__device__ float g_dw    [NOBJ*CD*HW];            // [n][c][p]
__device__ float g_pw    [NOBJ*HW*CD];            // [n][p][d]
__device__ float g_dwinv [CD];
__device__ float g_dwsh  [CD];
__device__ float g_partS [PW_PART_BLOCKS*CD];
__device__ float g_partQ [PW_PART_BLOCKS*CD];
__device__ float g_pwinv [CD];
__device__ float g_pwsh  [CD];
__device__ float g_SO    [NREL*NPIX*1024];
__device__ float g_flat  [NREL*FC1K];
__device__ float g_h1    [NREL*FCH];
__device__ float g_rel   [NREL*FCH];
__device__ float g_sub   [NOBJ*1024];
__device__ float g_cat   [NREL*1024];
__device__ float g_lo    [NREL*MAPN];
__device__ float g_lr    [NREL*MAPN];
__device__ float g_t     [NREL*MAPN];
__device__ float g_part  [16*256*4096];

// ---------------- helpers ----------------
__device__ __forceinline__ uint32_t smem_u32(const void* p) {
    uint32_t a;
    asm("{ .reg .u64 t; cvta.to.shared.u64 t, %1; cvt.u32.u64 %0, t; }" : "=r"(a) : "l"(p));
    return a;
}
__device__ __forceinline__ unsigned packbf(__nv_bfloat16 a, __nv_bfloat16 b) {
    __nv_bfloat162 t = __halves2bfloat162(a, b);
    return *reinterpret_cast<unsigned*>(&t);
}
__device__ __forceinline__ void split2(float x, __nv_bfloat16& h, __nv_bfloat16& l) {
    h = __float2bfloat16(x);
    l = __float2bfloat16(x - __bfloat162float(h));
}
__device__ __forceinline__ void mma_bf16(float* c, const uint32_t* a, const uint32_t* b) {
    asm volatile(
        "mma.sync.aligned.m16n8k16.row.col.f32.bf16.bf16.f32 "
        "{%0,%1,%2,%3}, {%4,%5,%6,%7}, {%8,%9}, {%0,%1,%2,%3};\n"
        : "+f"(c[0]), "+f"(c[1]), "+f"(c[2]), "+f"(c[3])
        : "r"(a[0]), "r"(a[1]), "r"(a[2]), "r"(a[3]), "r"(b[0]), "r"(b[1]));
}
__device__ __forceinline__ void ldsm4(uint32_t& r0, uint32_t& r1, uint32_t& r2, uint32_t& r3, uint32_t addr) {
    asm volatile("ldmatrix.sync.aligned.m8n8.x4.shared.b16 {%0,%1,%2,%3}, [%4];"
                 : "=r"(r0), "=r"(r1), "=r"(r2), "=r"(r3) : "r"(addr));
}
__device__ __forceinline__ void ldsm4t(uint32_t& r0, uint32_t& r1, uint32_t& r2, uint32_t& r3, uint32_t addr) {
    asm volatile("ldmatrix.sync.aligned.m8n8.x4.trans.shared.b16 {%0,%1,%2,%3}, [%4];"
                 : "=r"(r0), "=r"(r1), "=r"(r2), "=r"(r3) : "r"(addr));
}

// smem (K-chunk = 64): plane = 16KB. stage = Ah,Al,Bh,Bl = 64KB, double buffered = 128KB.
// m-major layout: 128 rows x 64 k bf16 (128B/row), chunk swizzle ^(row&7)
// k-major layout: 64 k-rows x 256B (128 m/n bf16), chunk swizzle ^(k&7)
#define PLANE   16384
#define STAGEB  65536
#define TG_SMEM 131072
__device__ __forceinline__ uint32_t offM(int row, int chunk) {
    return (uint32_t)(row * 128 + ((chunk ^ (row & 7)) << 4));
}
__device__ __forceinline__ uint32_t offK(int k, int chunk) {
    return (uint32_t)(k * 256 + ((chunk ^ (k & 7)) << 4));
}

// =====================================================================
// mma.sync bf16x3 GEMM. Tile 128x128, 512 threads (16 warps, 4x4 grid,
// warp tile 32x32). Double-buffered K=64 chunks, proven loop order:
// LDG(next) -> COMPUTE(cur) -> STS(next) -> bar.
// SRC_A/SRC_B: 0 = global m-major (X[row*ld+k]); 1 = global k-major (X[k*ld+row])
// BNA: a = a*inv[k]+sh[k].  BIAS 0/1(col)/2(row).  RELU.  OUTROI scatter.
// SPLITK: z = K-chunk of width kc (partials); else z = batch (sA,sB,sC).
// K (or kc) must be a multiple of 64.
// =====================================================================
template<int SRC_A, int SRC_B, bool BNA, int BIAS, bool RELU, bool OUTROI, bool SPLITK>
__global__ __launch_bounds__(512)
void tgemm(const float* __restrict__ A, const float* __restrict__ B,
           const float* __restrict__ bias, float* __restrict__ Cc,
           int M, int N, int K, int kc, int lda, int ldb, int ldc,
           long sA, long sB, long sC,
           const float* __restrict__ bninv, const float* __restrict__ bnsh)
{
    extern __shared__ char smc[];
    const uint32_t smem_base = smem_u32(smc);
    const int tid = threadIdx.x;
    const int lane = tid & 31, wid = tid >> 5;
    const int wm = wid >> 2, wn = wid & 3;     // 4x4 warps, warp tile 32x32
    const int g4 = lane >> 2, t4 = lane & 3;

    int k0;
    if (SPLITK) { k0 = blockIdx.z * kc; }
    else {
        A += (long)blockIdx.z * sA; B += (long)blockIdx.z * sB; Cc += (long)blockIdx.z * sC;
        k0 = 0;
    }
    const int m0 = blockIdx.y * 128;
    const int n0 = blockIdx.x * 128;
    const int nch = (SPLITK ? kc : K) / 64;

    const int ag = lane >> 3, ar = lane & 7;
    // non-trans fragment lane mapping (m-major planes)
    const int a_ml = ((ag & 1) << 3) + ar;
    const int a_kh = ag >> 1;
    const int b_nl = ((ag >> 1) << 3) + ar;
    const int b_kh = ag & 1;
    // trans fragment lane mapping (k-major planes)
    const int at_kr = ((ag >> 1) << 3) + ar;
    const int at_mc = ag & 1;
    const int bt_kr = ((ag & 1) << 3) + ar;
    const int bt_nc = ag >> 1;

    float acc[2][4][4];
#pragma unroll
    for (int a = 0; a < 2; a++)
#pragma unroll
        for (int b = 0; b < 4; b++)
#pragma unroll
            for (int c = 0; c < 4; c++) acc[a][b][c] = 0.f;

    float fa[16], fb[16];

    auto ldAg = [&](int kt) {
#pragma unroll
        for (int i = 0; i < 4; i++) {
            int e = tid + i * 512;
            if (SRC_A == 0) {
                int row = e >> 4, q = e & 15;
                int gm = m0 + row, gk = kt + q * 4;
                float4 v = make_float4(0.f, 0.f, 0.f, 0.f);
                if (gm < M) v = *reinterpret_cast<const float4*>(&A[(long)gm * lda + gk]);
                if (BNA) {
                    v.x = v.x * bninv[gk]   + bnsh[gk];
                    v.y = v.y * bninv[gk+1] + bnsh[gk+1];
                    v.z = v.z * bninv[gk+2] + bnsh[gk+2];
                    v.w = v.w * bninv[gk+3] + bnsh[gk+3];
                }
                fa[i*4+0]=v.x; fa[i*4+1]=v.y; fa[i*4+2]=v.z; fa[i*4+3]=v.w;
            } else {
                int k = e >> 5, mq = (e & 31) * 4;
                int gk = kt + k;
                float4 v = make_float4(0.f, 0.f, 0.f, 0.f);
                if (m0 + mq < M) v = *reinterpret_cast<const float4*>(&A[(long)gk * lda + m0 + mq]);
                if (BNA) {
                    float iv = bninv[gk], sv = bnsh[gk];
                    v.x = v.x*iv+sv; v.y = v.y*iv+sv; v.z = v.z*iv+sv; v.w = v.w*iv+sv;
                }
                fa[i*4+0]=v.x; fa[i*4+1]=v.y; fa[i*4+2]=v.z; fa[i*4+3]=v.w;
            }
        }
    };
    auto ldBg = [&](int kt) {
#pragma unroll
        for (int i = 0; i < 4; i++) {
            int e = tid + i * 512;
            if (SRC_B == 0) {
                int row = e >> 4, q = e & 15;
                int gn = n0 + row, gk = kt + q * 4;
                float4 v = make_float4(0.f, 0.f, 0.f, 0.f);
                if (gn < N) v = *reinterpret_cast<const float4*>(&B[(long)gn * ldb + gk]);
                fb[i*4+0]=v.x; fb[i*4+1]=v.y; fb[i*4+2]=v.z; fb[i*4+3]=v.w;
            } else {
                int k = e >> 5, nq = (e & 31) * 4;
                int gk = kt + k, gn = n0 + nq;
                float4 v;
                if (gn + 3 < N) v = *reinterpret_cast<const float4*>(&B[(long)gk * ldb + gn]);
                else {
                    v.x = (gn   < N) ? B[(long)gk * ldb + gn]   : 0.f;
                    v.y = (gn+1 < N) ? B[(long)gk * ldb + gn+1] : 0.f;
                    v.z = (gn+2 < N) ? B[(long)gk * ldb + gn+2] : 0.f;
                    v.w = (gn+3 < N) ? B[(long)gk * ldb + gn+3] : 0.f;
                }
                fb[i*4+0]=v.x; fb[i*4+1]=v.y; fb[i*4+2]=v.z; fb[i*4+3]=v.w;
            }
        }
    };
    auto stA = [&](int st) {
        char* hb = smc + st * STAGEB;
        char* lb = hb + PLANE;
#pragma unroll
        for (int i = 0; i < 4; i++) {
            int e = tid + i * 512;
            __nv_bfloat16 h[4], l[4];
#pragma unroll
            for (int j = 0; j < 4; j++) split2(fa[i*4+j], h[j], l[j]);
            uint32_t off;
            if (SRC_A == 0) {
                int row = e >> 4, q = e & 15;
                off = offM(row, q >> 1) + (uint32_t)((q & 1) << 3);
            } else {
                int k = e >> 5, mq = (e & 31) * 4;
                off = offK(k, mq >> 3) + (uint32_t)((mq & 7) << 1);
            }
            *reinterpret_cast<uint2*>(hb + off) = make_uint2(packbf(h[0],h[1]), packbf(h[2],h[3]));
            *reinterpret_cast<uint2*>(lb + off) = make_uint2(packbf(l[0],l[1]), packbf(l[2],l[3]));
        }
    };
    auto stB = [&](int st) {
        char* hb = smc + st * STAGEB + 2 * PLANE;
        char* lb = hb + PLANE;
#pragma unroll
        for (int i = 0; i < 4; i++) {
            int e = tid + i * 512;
            __nv_bfloat16 h[4], l[4];
#pragma unroll
            for (int j = 0; j < 4; j++) split2(fb[i*4+j], h[j], l[j]);
            uint32_t off;
            if (SRC_B == 0) {
                int row = e >> 4, q = e & 15;
                off = offM(row, q >> 1) + (uint32_t)((q & 1) << 3);
            } else {
                int k = e >> 5, nq = (e & 31) * 4;
                off = offK(k, nq >> 3) + (uint32_t)((nq & 7) << 1);
            }
            *reinterpret_cast<uint2*>(hb + off) = make_uint2(packbf(h[0],h[1]), packbf(h[2],h[3]));
            *reinterpret_cast<uint2*>(lb + off) = make_uint2(packbf(l[0],l[1]), packbf(l[2],l[3]));
        }
    };

    ldAg(k0); ldBg(k0);
    stA(0); stB(0);
    __syncthreads();

    int bb = 0;
    for (int c = 0; c < nch; c++) {
        bool nxt = (c + 1) < nch;
        if (nxt) { ldAg(k0 + (c + 1) * 64); ldBg(k0 + (c + 1) * 64); }

        uint32_t sb = smem_base + bb * STAGEB;
#pragma unroll
        for (int ks = 0; ks < 4; ks++) {
            uint32_t bhF[2][4], blF[2][4];
#pragma unroll
            for (int nh = 0; nh < 2; nh++) {
                if (SRC_B == 0) {
                    int n = wn * 32 + nh * 16 + b_nl;
                    uint32_t off = offM(n, ks * 2 + b_kh);
                    ldsm4(bhF[nh][0], bhF[nh][1], bhF[nh][2], bhF[nh][3], sb + 2*PLANE + off);
                    ldsm4(blF[nh][0], blF[nh][1], blF[nh][2], blF[nh][3], sb + 3*PLANE + off);
                } else {
                    int kr = ks * 16 + bt_kr;
                    int nc = wn * 4 + nh * 2 + bt_nc;
                    uint32_t off = offK(kr, nc);
                    ldsm4t(bhF[nh][0], bhF[nh][1], bhF[nh][2], bhF[nh][3], sb + 2*PLANE + off);
                    ldsm4t(blF[nh][0], blF[nh][1], blF[nh][2], blF[nh][3], sb + 3*PLANE + off);
                }
            }
#pragma unroll
            for (int mt = 0; mt < 2; mt++) {
                uint32_t ah[4], al[4];
                if (SRC_A == 0) {
                    int m = wm * 32 + mt * 16 + a_ml;
                    uint32_t off = offM(m, ks * 2 + a_kh);
                    ldsm4(ah[0], ah[1], ah[2], ah[3], sb + off);
                    ldsm4(al[0], al[1], al[2], al[3], sb + PLANE + off);
                } else {
                    int kr = ks * 16 + at_kr;
                    int mc = wm * 4 + mt * 2 + at_mc;
                    uint32_t off = offK(kr, mc);
                    ldsm4t(ah[0], ah[1], ah[2], ah[3], sb + off);
                    ldsm4t(al[0], al[1], al[2], al[3], sb + PLANE + off);
                }
#pragma unroll
                for (int nt = 0; nt < 4; nt++) {
                    const uint32_t* bh2 = &bhF[nt >> 1][(nt & 1) * 2];
                    const uint32_t* bl2 = &blF[nt >> 1][(nt & 1) * 2];
                    mma_bf16(acc[mt][nt], ah, bh2);
                    mma_bf16(acc[mt][nt], ah, bl2);
                    mma_bf16(acc[mt][nt], al, bh2);
                }
            }
        }
        if (!nxt) break;
        int nb = bb ^ 1;
        stA(nb); stB(nb);
        __syncthreads();
        bb = nb;
    }

    // ---- epilogue ----
#pragma unroll
    for (int mt = 0; mt < 2; mt++) {
#pragma unroll
        for (int nt = 0; nt < 4; nt++) {
#pragma unroll
            for (int e = 0; e < 4; e++) {
                int gm = m0 + wm * 32 + mt * 16 + g4 + ((e >= 2) ? 8 : 0);
                int gn = n0 + wn * 32 + nt * 8 + 2 * t4 + (e & 1);
                if (gm >= M || gn >= N) continue;
                float v = acc[mt][nt][e];
                if (SPLITK) {
                    Cc[((long)blockIdx.z * M + gm) * (long)N + gn] = v;
                } else {
                    if (BIAS == 1) v += bias[gn];
                    if (BIAS == 2) v += bias[gm];
                    if (RELU) v = fmaxf(v, 0.f);
                    long off;
                    if (OUTROI) { int r = gm / 49; int p = gm - r * 49; off = (long)r * FC1K + (long)gn * 49 + p; }
                    else        { off = (long)gm * ldc + gn; }
                    Cc[off] = v;
                }
            }
        }
    }
}

// ---------------- fp32 tiled SGEMM (comp only, split-K) ----------------
template<bool SPLITK>
__global__ __launch_bounds__(256)
void gemm_k(const float* __restrict__ A, const float* __restrict__ B,
            float* __restrict__ Cc, int M, int N, int K, int kc, int lda, int ldb)
{
    __shared__ float As[2][16][128];
    __shared__ float Bs[2][16][128];
    int k0 = blockIdx.z * kc, kend = k0 + kc;
    const int m0 = blockIdx.y * 128;
    const int n0 = blockIdx.x * 128;
    const int tid = threadIdx.x;
    const int tx = tid & 15;
    const int ty = tid >> 4;

    float acc[8][8];
#pragma unroll
    for (int i = 0; i < 8; i++)
#pragma unroll
        for (int j = 0; j < 8; j++) acc[i][j] = 0.f;

#pragma unroll
    for (int i = 0; i < 8; i++) {
        int idx = tid + i * 256;
        int m = idx >> 4, k = idx & 15;
        int gm = m0 + m, gk = k0 + k;
        As[0][k][m] = (gm < M) ? A[(long)gm * lda + gk] : 0.f;
    }
#pragma unroll
    for (int i = 0; i < 8; i++) {
        int idx = tid + i * 256;
        int k = idx >> 7, n = idx & 127;
        int gn = n0 + n, gk = k0 + k;
        Bs[0][k][n] = (gn < N) ? B[(long)gk * ldb + gn] : 0.f;
    }
    __syncthreads();

    int bb = 0;
    for (int kt = k0 + 16; ; kt += 16) {
        bool nxt = kt < kend;
        float ra[8], rb[8];
        if (nxt) {
#pragma unroll
            for (int i = 0; i < 8; i++) {
                int idx = tid + i * 256;
                int m = idx >> 4, k = idx & 15;
                int gm = m0 + m, gk = kt + k;
                ra[i] = (gm < M) ? A[(long)gm * lda + gk] : 0.f;
            }
#pragma unroll
            for (int i = 0; i < 8; i++) {
                int idx = tid + i * 256;
                int k = idx >> 7, n = idx & 127;
                int gn = n0 + n, gk = kt + k;
                rb[i] = (gn < N) ? B[(long)gk * ldb + gn] : 0.f;
            }
        }
#pragma unroll
        for (int k = 0; k < 16; k++) {
            float4 a0 = *reinterpret_cast<const float4*>(&As[bb][k][ty * 4]);
            float4 a1 = *reinterpret_cast<const float4*>(&As[bb][k][64 + ty * 4]);
            float4 b0 = *reinterpret_cast<const float4*>(&Bs[bb][k][tx * 4]);
            float4 b1 = *reinterpret_cast<const float4*>(&Bs[bb][k][64 + tx * 4]);
            float a[8] = {a0.x,a0.y,a0.z,a0.w,a1.x,a1.y,a1.z,a1.w};
            float b[8] = {b0.x,b0.y,b0.z,b0.w,b1.x,b1.y,b1.z,b1.w};
#pragma unroll
            for (int i = 0; i < 8; i++)
#pragma unroll
                for (int j = 0; j < 8; j++)
                    acc[i][j] += a[i] * b[j];
        }
        if (!nxt) break;
        int nb = bb ^ 1;
#pragma unroll
        for (int i = 0; i < 8; i++) {
            int idx = tid + i * 256;
            int m = idx >> 4, k = idx & 15;
            As[nb][k][m] = ra[i];
        }
#pragma unroll
        for (int i = 0; i < 8; i++) {
            int idx = tid + i * 256;
            int k = idx >> 7, n = idx & 127;
            Bs[nb][k][n] = rb[i];
        }
        __syncthreads();
        bb = nb;
    }

#pragma unroll
    for (int i = 0; i < 8; i++) {
        int gm = m0 + ((i < 4) ? ty * 4 + i : 64 + ty * 4 + (i - 4));
        if (gm >= M) continue;
#pragma unroll
        for (int j = 0; j < 8; j++) {
            int gn = n0 + ((j < 4) ? tx * 4 + j : 64 + tx * 4 + (j - 4));
            if (gn >= N) continue;
            Cc[((long)blockIdx.z * M + gm) * (long)N + gn] = acc[i][j];
        }
    }
}

// ---------------- skinny SGEMM: 64(M) x 128(N) ----------------
template<bool VECB, bool DIRECT, bool RELU>
__global__ __launch_bounds__(256)
void gemm_sk(const float* __restrict__ A, const float* __restrict__ B,
             const float* __restrict__ bias, float* __restrict__ Cc,
             int M, int N, int kc, int lda, int ldb, int ldc)
{
    __shared__ float As[2][16][64];
    __shared__ float Bs[2][16][128];
    const int m0 = blockIdx.y * 64, n0 = blockIdx.x * 128;
    const int k0 = blockIdx.z * kc;
    const int tid = threadIdx.x, tx = tid & 15, ty = tid >> 4;
    const int am = tid >> 2, akq = (tid & 3) * 4;
    const int bk = tid >> 4, bn = (tid & 15) * 8;

    float acc[4][8];
#pragma unroll
    for (int i = 0; i < 4; i++)
#pragma unroll
        for (int j = 0; j < 8; j++) acc[i][j] = 0.f;

    {
        float4 v = *reinterpret_cast<const float4*>(&A[(long)(m0 + am) * lda + k0 + akq]);
        As[0][akq + 0][am] = v.x; As[0][akq + 1][am] = v.y;
        As[0][akq + 2][am] = v.z; As[0][akq + 3][am] = v.w;
        if (VECB) {
            float4 b0v = *reinterpret_cast<const float4*>(&B[(long)(k0 + bk) * ldb + n0 + bn]);
            float4 b1v = *reinterpret_cast<const float4*>(&B[(long)(k0 + bk) * ldb + n0 + bn + 4]);
            *reinterpret_cast<float4*>(&Bs[0][bk][bn]) = b0v;
            *reinterpret_cast<float4*>(&Bs[0][bk][bn + 4]) = b1v;
        } else {
#pragma unroll
            for (int j = 0; j < 8; j++) {
                int gn = n0 + bn + j;
                Bs[0][bk][bn + j] = (gn < N) ? B[(long)(k0 + bk) * ldb + gn] : 0.f;
            }
        }
    }
    __syncthreads();

    int bb = 0;
    for (int kt = k0 + 16; ; kt += 16) {
        bool nxt = kt < k0 + kc;
        float4 va, vb0, vb1; float sb[8];
        if (nxt) {
            va = *reinterpret_cast<const float4*>(&A[(long)(m0 + am) * lda + kt + akq]);
            if (VECB) {
                vb0 = *reinterpret_cast<const float4*>(&B[(long)(kt + bk) * ldb + n0 + bn]);
                vb1 = *reinterpret_cast<const float4*>(&B[(long)(kt + bk) * ldb + n0 + bn + 4]);
            } else {
#pragma unroll
                for (int j = 0; j < 8; j++) {
                    int gn = n0 + bn + j;
                    sb[j] = (gn < N) ? B[(long)(kt + bk) * ldb + gn] : 0.f;
                }
            }
        }
#pragma unroll
        for (int k = 0; k < 16; k++) {
            float4 a0 = *reinterpret_cast<const float4*>(&As[bb][k][ty * 4]);
            float4 b0 = *reinterpret_cast<const float4*>(&Bs[bb][k][tx * 4]);
            float4 b1 = *reinterpret_cast<const float4*>(&Bs[bb][k][64 + tx * 4]);
            float a[4] = {a0.x,a0.y,a0.z,a0.w};
            float b[8] = {b0.x,b0.y,b0.z,b0.w,b1.x,b1.y,b1.z,b1.w};
#pragma unroll
            for (int i = 0; i < 4; i++)
#pragma unroll
                for (int j = 0; j < 8; j++)
                    acc[i][j] += a[i] * b[j];
        }
        if (!nxt) break;
        int nb = bb ^ 1;
        As[nb][akq + 0][am] = va.x; As[nb][akq + 1][am] = va.y;
        As[nb][akq + 2][am] = va.z; As[nb][akq + 3][am] = va.w;
        if (VECB) {
            *reinterpret_cast<float4*>(&Bs[nb][bk][bn]) = vb0;
            *reinterpret_cast<float4*>(&Bs[nb][bk][bn + 4]) = vb1;
        } else {
#pragma unroll
            for (int j = 0; j < 8; j++) Bs[nb][bk][bn + j] = sb[j];
        }
        __syncthreads();
        bb = nb;
    }

#pragma unroll
    for (int i = 0; i < 4; i++) {
        int gm = m0 + ty * 4 + i;
#pragma unroll
        for (int j = 0; j < 8; j++) {
            int gn = n0 + ((j < 4) ? tx * 4 + j : 64 + tx * 4 + (j - 4));
            if (gn >= N) continue;
            float v = acc[i][j];
            if (DIRECT) {
                v += bias[gn];
                if (RELU) v = fmaxf(v, 0.f);
                Cc[(long)gm * ldc + gn] = v;
            } else {
                Cc[((long)blockIdx.z * M + gm) * (long)N + gn] = v;
            }
        }
    }
}

// ---------------- split-K reduce ----------------
__global__ void reduce_k(const float* __restrict__ part, const float* __restrict__ bias,
                         float* __restrict__ C, int M, int N, int S, int ldc, int relu)
{
    int idx = blockIdx.x * 256 + threadIdx.x;
    if (idx >= M * N) return;
    int m = idx / N, n = idx - m * N;
    float v = 0.f;
    for (int s = 0; s < S; s++) v += part[(long)s * M * N + idx];
    v += bias[n];
    if (relu) v = fmaxf(v, 0.f);
    C[(long)m * ldc + n] = v;
}

// ---------------- depthwise 3x3 conv (padded smem, no bounds checks) ----------------
__global__ void dwconv_k(const float* __restrict__ rf, const float* __restrict__ dwf,
                         const int* __restrict__ im_inds, float* __restrict__ dw)
{
    int n = blockIdx.x, c = blockIdx.y;
    __shared__ float plane[40 * 40];
    __shared__ float f[9];
    int im = im_inds[n];
    const float* src = rf + ((long)im * CD + c) * HW;
    for (int i = threadIdx.x; i < 1600; i += 256) plane[i] = 0.f;
    if (threadIdx.x < 9) f[threadIdx.x] = dwf[((long)n * CD + c) * 9 + threadIdx.x];
    __syncthreads();
    for (int i = threadIdx.x; i < HW; i += 256) {
        int y = i / WF, x = i - y * WF;
        plane[(y + 1) * 40 + x + 1] = src[i];
    }
    __syncthreads();
    float* dst = dw + ((long)n * CD + c) * HW;
    for (int p = threadIdx.x; p < HW; p += 256) {
        int y = p / WF, x = p - y * WF;
        const float* b = &plane[y * 40 + x];
        float s = b[0]  * f[0] + b[1]  * f[1] + b[2]  * f[2]
                + b[40] * f[3] + b[41] * f[4] + b[42] * f[5]
                + b[80] * f[6] + b[81] * f[7] + b[82] * f[8];
        dst[p] = s;
    }
}

// ---------------- dw BN stats ----------------
__global__ void dwstats_k(const float* __restrict__ dw, const float* __restrict__ scale,
                          const float* __restrict__ bias, float* __restrict__ inv,
                          float* __restrict__ sh)
{
    int c = blockIdx.x;
    double s = 0.0, q = 0.0;
    for (int n = 0; n < NOBJ; n++) {
        const float* row = dw + ((long)n * CD + c) * HW;
        for (int p = threadIdx.x; p < HW; p += 256) {
            float v = row[p];
            s += v; q += (double)v * v;
        }
    }
    __shared__ double rs[256], rq[256];
    rs[threadIdx.x] = s; rq[threadIdx.x] = q;
    __syncthreads();
    for (int o = 128; o > 0; o >>= 1) {
        if (threadIdx.x < o) { rs[threadIdx.x] += rs[threadIdx.x + o]; rq[threadIdx.x] += rq[threadIdx.x + o]; }
        __syncthreads();
    }
    if (threadIdx.x == 0) {
        double cnt = (double)ROWS_PW;
        double m = rs[0] / cnt;
        double var = rq[0] / cnt - m * m;
        float iv = scale[c] * (float)(1.0 / sqrt(var + 1e-5));
        inv[c] = iv;
        sh[c]  = bias[c] - (float)m * iv;
    }
}

// ---------------- pw BN stats ----------------
__global__ void pwpart_k(const float* __restrict__ pw, float* __restrict__ pS, float* __restrict__ pQ)
{
    int blk = blockIdx.x;
    int t = threadIdx.x;
    float s0 = 0, q0 = 0, s1 = 0, q1 = 0;
    int r0 = blk * PW_ROWS_PER;
    int r1 = min(ROWS_PW, r0 + PW_ROWS_PER);
    for (int r = r0; r < r1; r++) {
        const float* row = pw + (long)r * CD;
        float v0 = row[t], v1 = row[t + 256];
        s0 += v0; q0 += v0 * v0;
        s1 += v1; q1 += v1 * v1;
    }
    pS[(long)blk * CD + t] = s0;       pS[(long)blk * CD + t + 256] = s1;
    pQ[(long)blk * CD + t] = q0;       pQ[(long)blk * CD + t + 256] = q1;
}

__global__ void pwfin_k(const float* __restrict__ pS, const float* __restrict__ pQ,
                        const float* __restrict__ scale, const float* __restrict__ bias,
                        float* __restrict__ inv, float* __restrict__ sh)
{
    int d = blockIdx.x;
    double s = 0.0, q = 0.0;
    for (int b = threadIdx.x; b < PW_PART_BLOCKS; b += 256) {
        s += pS[(long)b * CD + d];
        q += pQ[(long)b * CD + d];
    }
    __shared__ double rs[256], rq[256];
    rs[threadIdx.x] = s; rq[threadIdx.x] = q;
    __syncthreads();
    for (int o = 128; o > 0; o >>= 1) {
        if (threadIdx.x < o) { rs[threadIdx.x] += rs[threadIdx.x + o]; rq[threadIdx.x] += rq[threadIdx.x + o]; }
        __syncthreads();
    }
    if (threadIdx.x == 0) {
        double cnt = (double)ROWS_PW;
        double m = rs[0] / cnt;
        double var = rq[0] / cnt - m * m;
        float iv = scale[d] * (float)(1.0 / sqrt(var + 1e-5));
        inv[d] = iv;
        sh[d]  = bias[d] - (float)m * iv;
    }
}

// ---------------- ROI-align 7x7 with fused BN+ReLU ----------------
__global__ void roi_k(const float* __restrict__ pw, const float* __restrict__ boxes,
                      const int* __restrict__ rel_inds, const float* __restrict__ inv,
                      const float* __restrict__ sh, float* __restrict__ SO)
{
    int b = blockIdx.x;
    int r = b >> 1, role = b & 1;
    int obj = rel_inds[r * 2 + role];

    __shared__ int yi0[7], yi1[7], xi0[7], xi1[7];
    __shared__ float wy[7], wx[7];
    if (threadIdx.x < 14) {
        int i = threadIdx.x % 7;
        bool isY = threadIdx.x < 7;
        float lo = boxes[obj * 4 + (isY ? 1 : 0)] * (1.0f / 16.0f);
        float hi = boxes[obj * 4 + (isY ? 3 : 2)] * (1.0f / 16.0f);
        float g = ((float)i + 0.5f) / 7.0f;
        float v = lo + (hi - lo) * g;
        float f0 = floorf(v);
        float w = v - f0;
        int i0 = min(max((int)f0, 0), HF - 1);
        int i1 = min(i0 + 1, HF - 1);
        if (isY) { yi0[i] = i0; yi1[i] = i1; wy[i] = w; }
        else     { xi0[i] = i0; xi1[i] = i1; wx[i] = w; }
    }
    __syncthreads();

    const float* base = pw + (long)obj * HW * CD;
    float* dst = SO + (long)r * NPIX * 1024 + role * CD;

    for (int e = threadIdx.x; e < NPIX * CD; e += 256) {
        int pix = e >> 9;
        int c = e & 511;
        int iy = pix / 7, ix = pix - iy * 7;
        int y0 = yi0[iy], y1 = yi1[iy], x0 = xi0[ix], x1 = xi1[ix];
        float fy = wy[iy], fx = wx[ix];
        float ivv = inv[c], shv = sh[c];
        float v00 = fmaxf(base[(long)(y0 * WF + x0) * CD + c] * ivv + shv, 0.f);
        float v01 = fmaxf(base[(long)(y0 * WF + x1) * CD + c] * ivv + shv, 0.f);
        float v10 = fmaxf(base[(long)(y1 * WF + x0) * CD + c] * ivv + shv, 0.f);
        float v11 = fmaxf(base[(long)(y1 * WF + x1) * CD + c] * ivv + shv, 0.f);
        float out = v00 * (1.f - fy) * (1.f - fx) + v01 * (1.f - fy) * fx
                  + v10 * fy * (1.f - fx)         + v11 * fy * fx;
        dst[(long)pix * 1024 + c] = out;
    }
}

// ---------------- concat / triple ----------------
__global__ void cat_k(const float* __restrict__ sub, const int* __restrict__ rel_inds,
                      float* __restrict__ cat)
{
    int idx = blockIdx.x * 256 + threadIdx.x;
    if (idx >= NREL * 1024) return;
    int r = idx >> 10;
    int c = idx & 1023;
    int obj = rel_inds[r * 2 + (c < 512 ? 0 : 1)];
    cat[idx] = sub[(long)obj * 1024 + c];
}

__global__ void triple_k(const float* __restrict__ lo, const float* __restrict__ lr,
                         float* __restrict__ t)
{
    int idx = blockIdx.x * 256 + threadIdx.x;
    if (idx >= NREL * MAPN) return;
    float a = lo[idx], b = lr[idx];
    float d = a - b;
    t[idx] = fmaxf(a + b, 0.f) - d * d;
}

// ---------------- host ----------------
extern "C" void kernel_launch(void* const* d_in, const int* in_sizes, int n_in,
                              void* d_out, int out_size)
{
    (void)in_sizes; (void)n_in; (void)out_size;
    const float* fmaps     = (const float*)d_in[0];
    const float* boxes     = (const float*)d_in[1];
    const float* rof       = (const float*)d_in[2];
    const float* reduce_w  = (const float*)d_in[3];
    const float* reduce_b  = (const float*)d_in[4];
    const float* dw_gen_w  = (const float*)d_in[5];
    const float* dw_gen_b  = (const float*)d_in[6];
    const float* pw_gen_w  = (const float*)d_in[7];
    const float* pw_gen_b  = (const float*)d_in[8];
    const float* dw_bns    = (const float*)d_in[9];
    const float* dw_bnb    = (const float*)d_in[10];
    const float* pw_bns    = (const float*)d_in[11];
    const float* pw_bnb    = (const float*)d_in[12];
    const float* recover_w = (const float*)d_in[13];
    const float* recover_b = (const float*)d_in[14];
    const float* fc1_w     = (const float*)d_in[15];
    const float* fc1_b     = (const float*)d_in[16];
    const float* fc2_w     = (const float*)d_in[17];
    const float* fc2_b     = (const float*)d_in[18];
    const float* post_w    = (const float*)d_in[19];
    const float* post_b    = (const float*)d_in[20];
    const float* map_w     = (const float*)d_in[21];
    const float* map_b     = (const float*)d_in[22];
    const float* rr_w      = (const float*)d_in[23];
    const float* rr_b      = (const float*)d_in[24];
    const float* comp_w    = (const float*)d_in[25];
    const float* comp_b    = (const float*)d_in[26];
    const int*   im_inds   = (const int*)d_in[27];
    const int*   rel_inds  = (const int*)d_in[28];
    float* out = (float*)d_out;

    float *p_dwf, *p_pwf, *p_rf, *p_dw, *p_pw, *p_dwinv, *p_dwsh, *p_pS, *p_pQ,
          *p_pwinv, *p_pwsh, *p_SO, *p_flat, *p_h1, *p_rel, *p_sub, *p_cat,
          *p_lo, *p_lr, *p_t, *p_part;
    cudaGetSymbolAddress((void**)&p_dwf, g_dwf);
    cudaGetSymbolAddress((void**)&p_pwf, g_pwf);
    cudaGetSymbolAddress((void**)&p_rf, g_rf);
    cudaGetSymbolAddress((void**)&p_dw, g_dw);
    cudaGetSymbolAddress((void**)&p_pw, g_pw);
    cudaGetSymbolAddress((void**)&p_dwinv, g_dwinv);
    cudaGetSymbolAddress((void**)&p_dwsh, g_dwsh);
    cudaGetSymbolAddress((void**)&p_pS, g_partS);
    cudaGetSymbolAddress((void**)&p_pQ, g_partQ);
    cudaGetSymbolAddress((void**)&p_pwinv, g_pwinv);
    cudaGetSymbolAddress((void**)&p_pwsh, g_pwsh);
    cudaGetSymbolAddress((void**)&p_SO, g_SO);
    cudaGetSymbolAddress((void**)&p_flat, g_flat);
    cudaGetSymbolAddress((void**)&p_h1, g_h1);
    cudaGetSymbolAddress((void**)&p_rel, g_rel);
    cudaGetSymbolAddress((void**)&p_sub, g_sub);
    cudaGetSymbolAddress((void**)&p_cat, g_cat);
    cudaGetSymbolAddress((void**)&p_lo, g_lo);
    cudaGetSymbolAddress((void**)&p_lr, g_lr);
    cudaGetSymbolAddress((void**)&p_t, g_t);
    cudaGetSymbolAddress((void**)&p_part, g_part);

    auto T_pwf = tgemm<0,1,false,1,false,false,false>;
    auto T_rf  = tgemm<1,1,false,2,true ,false,false>;
    auto T_pwe = tgemm<1,0,true ,0,false,false,false>;
    auto T_rec = tgemm<0,1,false,1,false,true ,false>;
    auto T_sk  = tgemm<0,1,false,0,false,false,true >;
    cudaFuncSetAttribute(T_pwf, cudaFuncAttributeMaxDynamicSharedMemorySize, TG_SMEM);
    cudaFuncSetAttribute(T_rf , cudaFuncAttributeMaxDynamicSharedMemorySize, TG_SMEM);
    cudaFuncSetAttribute(T_pwe, cudaFuncAttributeMaxDynamicSharedMemorySize, TG_SMEM);
    cudaFuncSetAttribute(T_rec, cudaFuncAttributeMaxDynamicSharedMemorySize, TG_SMEM);
    cudaFuncSetAttribute(T_sk , cudaFuncAttributeMaxDynamicSharedMemorySize, TG_SMEM);

    // 1) dw_f = rof @ dw_gen_w + b (fp32 skinny split-K)
    gemm_sk<true,false,false><<<dim3(36,1,4),256>>>(
        rof, dw_gen_w, nullptr, p_part, 64,4608,128, 512,4608,0);
    reduce_k<<<(64*4608+255)/256,256>>>(p_part, dw_gen_b, p_dwf, 64,4608,4,4608,0);

    // 2) pw_f = rof @ pw_gen_w + b  (M=64 in a 128 tile)
    T_pwf<<<dim3(2048,1,1),512,TG_SMEM>>>(
        rof, pw_gen_w, pw_gen_b, p_pwf, 64,262144,512,0, 512,262144,262144,
        0,0,0, nullptr,nullptr);

    // 3) rf[b][o][p] = relu(W^T fm + b)
    T_rf<<<dim3(12,4,2),512,TG_SMEM>>>(
        reduce_w, fmaps, reduce_b, p_rf, CD,HW,CD,0, CD,HW,HW,
        0, (long)CD*HW, (long)CD*HW, nullptr,nullptr);

    // 4) depthwise conv
    dwconv_k<<<dim3(NOBJ,CD),256>>>(p_rf, p_dwf, im_inds, p_dw);

    // 5) dw BN params
    dwstats_k<<<CD,256>>>(p_dw, dw_bns, dw_bnb, p_dwinv, p_dwsh);

    // 6) pw[n][p][d] = bn(dw^T) @ pwf^T   (batch 64)
    T_pwe<<<dim3(4,12,64),512,TG_SMEM>>>(
        p_dw, p_pwf, nullptr, p_pw, HW,CD,CD,0, HW,CD,CD,
        (long)CD*HW, (long)CD*CD, (long)HW*CD, p_dwinv, p_dwsh);

    // 7) pw BN stats
    pwpart_k<<<PW_PART_BLOCKS,256>>>(p_pw, p_pS, p_pQ);
    pwfin_k<<<CD,256>>>(p_pS, p_pQ, pw_bns, pw_bnb, p_pwinv, p_pwsh);

    // 8) ROI align
    roi_k<<<NREL*2,256>>>(p_pw, boxes, rel_inds, p_pwinv, p_pwsh, p_SO);

    // 9) rec = SO @ recover_w + b, ROI scatter
    T_rec<<<dim3(4,98,1),512,TG_SMEM>>>(
        p_SO, recover_w, recover_b, p_flat, NREL*NPIX,CD,1024,0, 1024,CD,0,
        0,0,0, nullptr,nullptr);

    // 10) fc1 (split-K S=8, kc=3136 = 49*64)
    T_sk<<<dim3(32,2,8),512,TG_SMEM>>>(
        p_flat, fc1_w, nullptr, p_part, NREL,FCH,FC1K,3136, FC1K,FCH,0,
        0,0,0, nullptr,nullptr);
    reduce_k<<<(NREL*FCH+255)/256,256>>>(p_part, fc1_b, p_h1, NREL,FCH,8,FCH,1);

    // 11) fc2 (split-K S=8, kc=512)
    T_sk<<<dim3(32,2,8),512,TG_SMEM>>>(
        p_h1, fc2_w, nullptr, p_part, NREL,FCH,FCH,512, FCH,FCH,0,
        0,0,0, nullptr,nullptr);
    reduce_k<<<(NREL*FCH+255)/256,256>>>(p_part, fc2_b, p_rel, NREL,FCH,8,FCH,0);

    // 12) subobj (fp32 skinny)
    gemm_sk<true,false,false><<<dim3(8,1,8),256>>>(
        rof, post_w, nullptr, p_part, 64,1024,64, 512,1024,0);
    reduce_k<<<(64*1024+255)/256,256>>>(p_part, post_b, p_sub, 64,1024,8,1024,0);

    // 13) cat
    cat_k<<<(NREL*1024+255)/256,256>>>(p_sub, rel_inds, p_cat);

    // 14) last_obj (split-K S=8, kc=128)
    T_sk<<<dim3(12,2,8),512,TG_SMEM>>>(
        p_cat, map_w, nullptr, p_part, NREL,MAPN,1024,128, 1024,MAPN,0,
        0,0,0, nullptr,nullptr);
    reduce_k<<<(NREL*MAPN+255)/256,256>>>(p_part, map_b, p_lo, NREL,MAPN,8,MAPN,0);

    // 15) last_rel (split-K S=16, kc=256)
    T_sk<<<dim3(12,2,16),512,TG_SMEM>>>(
        p_rel, rr_w, nullptr, p_part, NREL,MAPN,FCH,256, FCH,MAPN,0,
        0,0,0, nullptr,nullptr);
    reduce_k<<<(NREL*MAPN+255)/256,256>>>(p_part, rr_b, p_lr, NREL,MAPN,16,MAPN,0);

    // 16) triple
    triple_k<<<(NREL*MAPN+255)/256,256>>>(p_lo, p_lr, p_t);

    // 17) comp (fp32, N=51, split-K S=8)
    gemm_k<true><<<dim3(1,2,8),256>>>(
        p_t, comp_w, p_part, NREL,OUTN,MAPN,192, MAPN,OUTN);
    reduce_k<<<(NREL*OUTN+255)/256,256>>>(p_part, comp_b, out, NREL,OUTN,8,OUTN,0);
}

// round 14
// speedup vs baseline: 1.1930x; 1.0116x over previous
#include <cuda_runtime.h>
#include <cuda_bf16.h>
#include <math.h>
#include <stdint.h>

// ---------------- problem constants ----------------
#define CD     512
#define HF     38
#define WF     38
#define HW     1444
#define NOBJ   64
#define NREL   256
#define NIMG   2
#define NPIX   49
#define FC1K   25088
#define FCH    4096
#define MAPN   1536
#define OUTN   51
#define ROWS_PW 92416
#define PW_PART_BLOCKS 1024
#define PW_ROWS_PER 91

// ---------------- scratch ----------------
__device__ float g_dwf   [NOBJ*4608];
__device__ float g_pwf   [NOBJ*CD*CD];
__device__ float g_rf    [NIMG*CD*HW];
__device__ float g_dw    [NOBJ*CD*HW];            // [n][c][p]
__device__ float g_pw    [NOBJ*HW*CD];            // [n][p][d]
__device__ float g_dwinv [CD];
__device__ float g_dwsh  [CD];
__device__ float g_partS [PW_PART_BLOCKS*CD];
__device__ float g_partQ [PW_PART_BLOCKS*CD];
__device__ float g_pwinv [CD];
__device__ float g_pwsh  [CD];
__device__ float g_SO    [NREL*NPIX*1024];
__device__ float g_flat  [NREL*FC1K];
__device__ float g_h1    [NREL*FCH];
__device__ float g_rel   [NREL*FCH];
__device__ float g_sub   [NOBJ*1024];
__device__ float g_cat   [NREL*1024];
__device__ float g_lo    [NREL*MAPN];
__device__ float g_lr    [NREL*MAPN];
__device__ float g_t     [NREL*MAPN];
__device__ float g_part  [16*256*4096];           // 16.78M floats; stream-disjoint regions

// ---------------- helpers ----------------
__device__ __forceinline__ uint32_t smem_u32(const void* p) {
    uint32_t a;
    asm("{ .reg .u64 t; cvta.to.shared.u64 t, %1; cvt.u32.u64 %0, t; }" : "=r"(a) : "l"(p));
    return a;
}
__device__ __forceinline__ unsigned packbf(__nv_bfloat16 a, __nv_bfloat16 b) {
    __nv_bfloat162 t = __halves2bfloat162(a, b);
    return *reinterpret_cast<unsigned*>(&t);
}
__device__ __forceinline__ void split2(float x, __nv_bfloat16& h, __nv_bfloat16& l) {
    h = __float2bfloat16(x);
    l = __float2bfloat16(x - __bfloat162float(h));
}
__device__ __forceinline__ void mma_bf16(float* c, const uint32_t* a, const uint32_t* b) {
    asm volatile(
        "mma.sync.aligned.m16n8k16.row.col.f32.bf16.bf16.f32 "
        "{%0,%1,%2,%3}, {%4,%5,%6,%7}, {%8,%9}, {%0,%1,%2,%3};\n"
        : "+f"(c[0]), "+f"(c[1]), "+f"(c[2]), "+f"(c[3])
        : "r"(a[0]), "r"(a[1]), "r"(a[2]), "r"(a[3]), "r"(b[0]), "r"(b[1]));
}
__device__ __forceinline__ void ldsm4(uint32_t& r0, uint32_t& r1, uint32_t& r2, uint32_t& r3, uint32_t addr) {
    asm volatile("ldmatrix.sync.aligned.m8n8.x4.shared.b16 {%0,%1,%2,%3}, [%4];"
                 : "=r"(r0), "=r"(r1), "=r"(r2), "=r"(r3) : "r"(addr));
}
__device__ __forceinline__ void ldsm4t(uint32_t& r0, uint32_t& r1, uint32_t& r2, uint32_t& r3, uint32_t addr) {
    asm volatile("ldmatrix.sync.aligned.m8n8.x4.trans.shared.b16 {%0,%1,%2,%3}, [%4];"
                 : "=r"(r0), "=r"(r1), "=r"(r2), "=r"(r3) : "r"(addr));
}

// smem (K-chunk = 64): plane = 16KB. stage = Ah,Al,Bh,Bl = 64KB, double buffered = 128KB.
// m-major layout: 128 rows x 64 k bf16 (128B/row), chunk swizzle ^(row&7)
// k-major layout: 64 k-rows x 256B (128 m/n bf16), chunk swizzle ^(k&7)
#define PLANE   16384
#define STAGEB  65536
#define TG_SMEM 131072
__device__ __forceinline__ uint32_t offM(int row, int chunk) {
    return (uint32_t)(row * 128 + ((chunk ^ (row & 7)) << 4));
}
__device__ __forceinline__ uint32_t offK(int k, int chunk) {
    return (uint32_t)(k * 256 + ((chunk ^ (k & 7)) << 4));
}

// =====================================================================
// mma.sync bf16x3 GEMM. Tile 128x128, 512 threads (16 warps, 4x4 grid,
// warp tile 32x32). Double-buffered K=64 chunks, proven loop order:
// LDG(next) -> COMPUTE(cur) -> STS(next) -> bar.
// SRC_A/SRC_B: 0 = global m-major (X[row*ld+k]); 1 = global k-major (X[k*ld+row])
// BNA: a = a*inv[k]+sh[k].  BIAS 0/1(col)/2(row).  RELU.  OUTROI scatter.
// SPLITK: z = K-chunk of width kc (partials); else z = batch (sA,sB,sC).
// K (or kc) must be a multiple of 64.
// =====================================================================
template<int SRC_A, int SRC_B, bool BNA, int BIAS, bool RELU, bool OUTROI, bool SPLITK>
__global__ __launch_bounds__(512)
void tgemm(const float* __restrict__ A, const float* __restrict__ B,
           const float* __restrict__ bias, float* __restrict__ Cc,
           int M, int N, int K, int kc, int lda, int ldb, int ldc,
           long sA, long sB, long sC,
           const float* __restrict__ bninv, const float* __restrict__ bnsh)
{
    extern __shared__ char smc[];
    const uint32_t smem_base = smem_u32(smc);
    const int tid = threadIdx.x;
    const int lane = tid & 31, wid = tid >> 5;
    const int wm = wid >> 2, wn = wid & 3;     // 4x4 warps, warp tile 32x32
    const int g4 = lane >> 2, t4 = lane & 3;

    int k0;
    if (SPLITK) { k0 = blockIdx.z * kc; }
    else {
        A += (long)blockIdx.z * sA; B += (long)blockIdx.z * sB; Cc += (long)blockIdx.z * sC;
        k0 = 0;
    }
    const int m0 = blockIdx.y * 128;
    const int n0 = blockIdx.x * 128;
    const int nch = (SPLITK ? kc : K) / 64;

    const int ag = lane >> 3, ar = lane & 7;
    // non-trans fragment lane mapping (m-major planes)
    const int a_ml = ((ag & 1) << 3) + ar;
    const int a_kh = ag >> 1;
    const int b_nl = ((ag >> 1) << 3) + ar;
    const int b_kh = ag & 1;
    // trans fragment lane mapping (k-major planes)
    const int at_kr = ((ag >> 1) << 3) + ar;
    const int at_mc = ag & 1;
    const int bt_kr = ((ag & 1) << 3) + ar;
    const int bt_nc = ag >> 1;

    float acc[2][4][4];
#pragma unroll
    for (int a = 0; a < 2; a++)
#pragma unroll
        for (int b = 0; b < 4; b++)
#pragma unroll
            for (int c = 0; c < 4; c++) acc[a][b][c] = 0.f;

    float fa[16], fb[16];

    auto ldAg = [&](int kt) {
#pragma unroll
        for (int i = 0; i < 4; i++) {
            int e = tid + i * 512;
            if (SRC_A == 0) {
                int row = e >> 4, q = e & 15;
                int gm = m0 + row, gk = kt + q * 4;
                float4 v = make_float4(0.f, 0.f, 0.f, 0.f);
                if (gm < M) v = *reinterpret_cast<const float4*>(&A[(long)gm * lda + gk]);
                if (BNA) {
                    v.x = v.x * bninv[gk]   + bnsh[gk];
                    v.y = v.y * bninv[gk+1] + bnsh[gk+1];
                    v.z = v.z * bninv[gk+2] + bnsh[gk+2];
                    v.w = v.w * bninv[gk+3] + bnsh[gk+3];
                }
                fa[i*4+0]=v.x; fa[i*4+1]=v.y; fa[i*4+2]=v.z; fa[i*4+3]=v.w;
            } else {
                int k = e >> 5, mq = (e & 31) * 4;
                int gk = kt + k;
                float4 v = make_float4(0.f, 0.f, 0.f, 0.f);
                if (m0 + mq < M) v = *reinterpret_cast<const float4*>(&A[(long)gk * lda + m0 + mq]);
                if (BNA) {
                    float iv = bninv[gk], sv = bnsh[gk];
                    v.x = v.x*iv+sv; v.y = v.y*iv+sv; v.z = v.z*iv+sv; v.w = v.w*iv+sv;
                }
                fa[i*4+0]=v.x; fa[i*4+1]=v.y; fa[i*4+2]=v.z; fa[i*4+3]=v.w;
            }
        }
    };
    auto ldBg = [&](int kt) {
#pragma unroll
        for (int i = 0; i < 4; i++) {
            int e = tid + i * 512;
            if (SRC_B == 0) {
                int row = e >> 4, q = e & 15;
                int gn = n0 + row, gk = kt + q * 4;
                float4 v = make_float4(0.f, 0.f, 0.f, 0.f);
                if (gn < N) v = *reinterpret_cast<const float4*>(&B[(long)gn * ldb + gk]);
                fb[i*4+0]=v.x; fb[i*4+1]=v.y; fb[i*4+2]=v.z; fb[i*4+3]=v.w;
            } else {
                int k = e >> 5, nq = (e & 31) * 4;
                int gk = kt + k, gn = n0 + nq;
                float4 v;
                if (gn + 3 < N) v = *reinterpret_cast<const float4*>(&B[(long)gk * ldb + gn]);
                else {
                    v.x = (gn   < N) ? B[(long)gk * ldb + gn]   : 0.f;
                    v.y = (gn+1 < N) ? B[(long)gk * ldb + gn+1] : 0.f;
                    v.z = (gn+2 < N) ? B[(long)gk * ldb + gn+2] : 0.f;
                    v.w = (gn+3 < N) ? B[(long)gk * ldb + gn+3] : 0.f;
                }
                fb[i*4+0]=v.x; fb[i*4+1]=v.y; fb[i*4+2]=v.z; fb[i*4+3]=v.w;
            }
        }
    };
    auto stA = [&](int st) {
        char* hb = smc + st * STAGEB;
        char* lb = hb + PLANE;
#pragma unroll
        for (int i = 0; i < 4; i++) {
            int e = tid + i * 512;
            __nv_bfloat16 h[4], l[4];
#pragma unroll
            for (int j = 0; j < 4; j++) split2(fa[i*4+j], h[j], l[j]);
            uint32_t off;
            if (SRC_A == 0) {
                int row = e >> 4, q = e & 15;
                off = offM(row, q >> 1) + (uint32_t)((q & 1) << 3);
            } else {
                int k = e >> 5, mq = (e & 31) * 4;
                off = offK(k, mq >> 3) + (uint32_t)((mq & 7) << 1);
            }
            *reinterpret_cast<uint2*>(hb + off) = make_uint2(packbf(h[0],h[1]), packbf(h[2],h[3]));
            *reinterpret_cast<uint2*>(lb + off) = make_uint2(packbf(l[0],l[1]), packbf(l[2],l[3]));
        }
    };
    auto stB = [&](int st) {
        char* hb = smc + st * STAGEB + 2 * PLANE;
        char* lb = hb + PLANE;
#pragma unroll
        for (int i = 0; i < 4; i++) {
            int e = tid + i * 512;
            __nv_bfloat16 h[4], l[4];
#pragma unroll
            for (int j = 0; j < 4; j++) split2(fb[i*4+j], h[j], l[j]);
            uint32_t off;
            if (SRC_B == 0) {
                int row = e >> 4, q = e & 15;
                off = offM(row, q >> 1) + (uint32_t)((q & 1) << 3);
            } else {
                int k = e >> 5, nq = (e & 31) * 4;
                off = offK(k, nq >> 3) + (uint32_t)((nq & 7) << 1);
            }
            *reinterpret_cast<uint2*>(hb + off) = make_uint2(packbf(h[0],h[1]), packbf(h[2],h[3]));
            *reinterpret_cast<uint2*>(lb + off) = make_uint2(packbf(l[0],l[1]), packbf(l[2],l[3]));
        }
    };

    ldAg(k0); ldBg(k0);
    stA(0); stB(0);
    __syncthreads();

    int bb = 0;
    for (int c = 0; c < nch; c++) {
        bool nxt = (c + 1) < nch;
        if (nxt) { ldAg(k0 + (c + 1) * 64); ldBg(k0 + (c + 1) * 64); }

        uint32_t sb = smem_base + bb * STAGEB;
#pragma unroll
        for (int ks = 0; ks < 4; ks++) {
            uint32_t bhF[2][4], blF[2][4];
#pragma unroll
            for (int nh = 0; nh < 2; nh++) {
                if (SRC_B == 0) {
                    int n = wn * 32 + nh * 16 + b_nl;
                    uint32_t off = offM(n, ks * 2 + b_kh);
                    ldsm4(bhF[nh][0], bhF[nh][1], bhF[nh][2], bhF[nh][3], sb + 2*PLANE + off);
                    ldsm4(blF[nh][0], blF[nh][1], blF[nh][2], blF[nh][3], sb + 3*PLANE + off);
                } else {
                    int kr = ks * 16 + bt_kr;
                    int nc = wn * 4 + nh * 2 + bt_nc;
                    uint32_t off = offK(kr, nc);
                    ldsm4t(bhF[nh][0], bhF[nh][1], bhF[nh][2], bhF[nh][3], sb + 2*PLANE + off);
                    ldsm4t(blF[nh][0], blF[nh][1], blF[nh][2], blF[nh][3], sb + 3*PLANE + off);
                }
            }
#pragma unroll
            for (int mt = 0; mt < 2; mt++) {
                uint32_t ah[4], al[4];
                if (SRC_A == 0) {
                    int m = wm * 32 + mt * 16 + a_ml;
                    uint32_t off = offM(m, ks * 2 + a_kh);
                    ldsm4(ah[0], ah[1], ah[2], ah[3], sb + off);
                    ldsm4(al[0], al[1], al[2], al[3], sb + PLANE + off);
                } else {
                    int kr = ks * 16 + at_kr;
                    int mc = wm * 4 + mt * 2 + at_mc;
                    uint32_t off = offK(kr, mc);
                    ldsm4t(ah[0], ah[1], ah[2], ah[3], sb + off);
                    ldsm4t(al[0], al[1], al[2], al[3], sb + PLANE + off);
                }
#pragma unroll
                for (int nt = 0; nt < 4; nt++) {
                    const uint32_t* bh2 = &bhF[nt >> 1][(nt & 1) * 2];
                    const uint32_t* bl2 = &blF[nt >> 1][(nt & 1) * 2];
                    mma_bf16(acc[mt][nt], ah, bh2);
                    mma_bf16(acc[mt][nt], ah, bl2);
                    mma_bf16(acc[mt][nt], al, bh2);
                }
            }
        }
        if (!nxt) break;
        int nb = bb ^ 1;
        stA(nb); stB(nb);
        __syncthreads();
        bb = nb;
    }

    // ---- epilogue ----
#pragma unroll
    for (int mt = 0; mt < 2; mt++) {
#pragma unroll
        for (int nt = 0; nt < 4; nt++) {
#pragma unroll
            for (int e = 0; e < 4; e++) {
                int gm = m0 + wm * 32 + mt * 16 + g4 + ((e >= 2) ? 8 : 0);
                int gn = n0 + wn * 32 + nt * 8 + 2 * t4 + (e & 1);
                if (gm >= M || gn >= N) continue;
                float v = acc[mt][nt][e];
                if (SPLITK) {
                    Cc[((long)blockIdx.z * M + gm) * (long)N + gn] = v;
                } else {
                    if (BIAS == 1) v += bias[gn];
                    if (BIAS == 2) v += bias[gm];
                    if (RELU) v = fmaxf(v, 0.f);
                    long off;
                    if (OUTROI) { int r = gm / 49; int p = gm - r * 49; off = (long)r * FC1K + (long)gn * 49 + p; }
                    else        { off = (long)gm * ldc + gn; }
                    Cc[off] = v;
                }
            }
        }
    }
}

// ---------------- fp32 tiled SGEMM (comp only, split-K) ----------------
template<bool SPLITK>
__global__ __launch_bounds__(256)
void gemm_k(const float* __restrict__ A, const float* __restrict__ B,
            float* __restrict__ Cc, int M, int N, int K, int kc, int lda, int ldb)
{
    __shared__ float As[2][16][128];
    __shared__ float Bs[2][16][128];
    int k0 = blockIdx.z * kc, kend = k0 + kc;
    const int m0 = blockIdx.y * 128;
    const int n0 = blockIdx.x * 128;
    const int tid = threadIdx.x;
    const int tx = tid & 15;
    const int ty = tid >> 4;

    float acc[8][8];
#pragma unroll
    for (int i = 0; i < 8; i++)
#pragma unroll
        for (int j = 0; j < 8; j++) acc[i][j] = 0.f;

#pragma unroll
    for (int i = 0; i < 8; i++) {
        int idx = tid + i * 256;
        int m = idx >> 4, k = idx & 15;
        int gm = m0 + m, gk = k0 + k;
        As[0][k][m] = (gm < M) ? A[(long)gm * lda + gk] : 0.f;
    }
#pragma unroll
    for (int i = 0; i < 8; i++) {
        int idx = tid + i * 256;
        int k = idx >> 7, n = idx & 127;
        int gn = n0 + n, gk = k0 + k;
        Bs[0][k][n] = (gn < N) ? B[(long)gk * ldb + gn] : 0.f;
    }
    __syncthreads();

    int bb = 0;
    for (int kt = k0 + 16; ; kt += 16) {
        bool nxt = kt < kend;
        float ra[8], rb[8];
        if (nxt) {
#pragma unroll
            for (int i = 0; i < 8; i++) {
                int idx = tid + i * 256;
                int m = idx >> 4, k = idx & 15;
                int gm = m0 + m, gk = kt + k;
                ra[i] = (gm < M) ? A[(long)gm * lda + gk] : 0.f;
            }
#pragma unroll
            for (int i = 0; i < 8; i++) {
                int idx = tid + i * 256;
                int k = idx >> 7, n = idx & 127;
                int gn = n0 + n, gk = kt + k;
                rb[i] = (gn < N) ? B[(long)gk * ldb + gn] : 0.f;
            }
        }
#pragma unroll
        for (int k = 0; k < 16; k++) {
            float4 a0 = *reinterpret_cast<const float4*>(&As[bb][k][ty * 4]);
            float4 a1 = *reinterpret_cast<const float4*>(&As[bb][k][64 + ty * 4]);
            float4 b0 = *reinterpret_cast<const float4*>(&Bs[bb][k][tx * 4]);
            float4 b1 = *reinterpret_cast<const float4*>(&Bs[bb][k][64 + tx * 4]);
            float a[8] = {a0.x,a0.y,a0.z,a0.w,a1.x,a1.y,a1.z,a1.w};
            float b[8] = {b0.x,b0.y,b0.z,b0.w,b1.x,b1.y,b1.z,b1.w};
#pragma unroll
            for (int i = 0; i < 8; i++)
#pragma unroll
                for (int j = 0; j < 8; j++)
                    acc[i][j] += a[i] * b[j];
        }
        if (!nxt) break;
        int nb = bb ^ 1;
#pragma unroll
        for (int i = 0; i < 8; i++) {
            int idx = tid + i * 256;
            int m = idx >> 4, k = idx & 15;
            As[nb][k][m] = ra[i];
        }
#pragma unroll
        for (int i = 0; i < 8; i++) {
            int idx = tid + i * 256;
            int k = idx >> 7, n = idx & 127;
            Bs[nb][k][n] = rb[i];
        }
        __syncthreads();
        bb = nb;
    }

#pragma unroll
    for (int i = 0; i < 8; i++) {
        int gm = m0 + ((i < 4) ? ty * 4 + i : 64 + ty * 4 + (i - 4));
        if (gm >= M) continue;
#pragma unroll
        for (int j = 0; j < 8; j++) {
            int gn = n0 + ((j < 4) ? tx * 4 + j : 64 + tx * 4 + (j - 4));
            if (gn >= N) continue;
            Cc[((long)blockIdx.z * M + gm) * (long)N + gn] = acc[i][j];
        }
    }
}

// ---------------- skinny SGEMM: 64(M) x 128(N) ----------------
template<bool VECB, bool DIRECT, bool RELU>
__global__ __launch_bounds__(256)
void gemm_sk(const float* __restrict__ A, const float* __restrict__ B,
             const float* __restrict__ bias, float* __restrict__ Cc,
             int M, int N, int kc, int lda, int ldb, int ldc)
{
    __shared__ float As[2][16][64];
    __shared__ float Bs[2][16][128];
    const int m0 = blockIdx.y * 64, n0 = blockIdx.x * 128;
    const int k0 = blockIdx.z * kc;
    const int tid = threadIdx.x, tx = tid & 15, ty = tid >> 4;
    const int am = tid >> 2, akq = (tid & 3) * 4;
    const int bk = tid >> 4, bn = (tid & 15) * 8;

    float acc[4][8];
#pragma unroll
    for (int i = 0; i < 4; i++)
#pragma unroll
        for (int j = 0; j < 8; j++) acc[i][j] = 0.f;

    {
        float4 v = *reinterpret_cast<const float4*>(&A[(long)(m0 + am) * lda + k0 + akq]);
        As[0][akq + 0][am] = v.x; As[0][akq + 1][am] = v.y;
        As[0][akq + 2][am] = v.z; As[0][akq + 3][am] = v.w;
        if (VECB) {
            float4 b0v = *reinterpret_cast<const float4*>(&B[(long)(k0 + bk) * ldb + n0 + bn]);
            float4 b1v = *reinterpret_cast<const float4*>(&B[(long)(k0 + bk) * ldb + n0 + bn + 4]);
            *reinterpret_cast<float4*>(&Bs[0][bk][bn]) = b0v;
            *reinterpret_cast<float4*>(&Bs[0][bk][bn + 4]) = b1v;
        } else {
#pragma unroll
            for (int j = 0; j < 8; j++) {
                int gn = n0 + bn + j;
                Bs[0][bk][bn + j] = (gn < N) ? B[(long)(k0 + bk) * ldb + gn] : 0.f;
            }
        }
    }
    __syncthreads();

    int bb = 0;
    for (int kt = k0 + 16; ; kt += 16) {
        bool nxt = kt < k0 + kc;
        float4 va, vb0, vb1; float sb[8];
        if (nxt) {
            va = *reinterpret_cast<const float4*>(&A[(long)(m0 + am) * lda + kt + akq]);
            if (VECB) {
                vb0 = *reinterpret_cast<const float4*>(&B[(long)(kt + bk) * ldb + n0 + bn]);
                vb1 = *reinterpret_cast<const float4*>(&B[(long)(kt + bk) * ldb + n0 + bn + 4]);
            } else {
#pragma unroll
                for (int j = 0; j < 8; j++) {
                    int gn = n0 + bn + j;
                    sb[j] = (gn < N) ? B[(long)(kt + bk) * ldb + gn] : 0.f;
                }
            }
        }
#pragma unroll
        for (int k = 0; k < 16; k++) {
            float4 a0 = *reinterpret_cast<const float4*>(&As[bb][k][ty * 4]);
            float4 b0 = *reinterpret_cast<const float4*>(&Bs[bb][k][tx * 4]);
            float4 b1 = *reinterpret_cast<const float4*>(&Bs[bb][k][64 + tx * 4]);
            float a[4] = {a0.x,a0.y,a0.z,a0.w};
            float b[8] = {b0.x,b0.y,b0.z,b0.w,b1.x,b1.y,b1.z,b1.w};
#pragma unroll
            for (int i = 0; i < 4; i++)
#pragma unroll
                for (int j = 0; j < 8; j++)
                    acc[i][j] += a[i] * b[j];
        }
        if (!nxt) break;
        int nb = bb ^ 1;
        As[nb][akq + 0][am] = va.x; As[nb][akq + 1][am] = va.y;
        As[nb][akq + 2][am] = va.z; As[nb][akq + 3][am] = va.w;
        if (VECB) {
            *reinterpret_cast<float4*>(&Bs[nb][bk][bn]) = vb0;
            *reinterpret_cast<float4*>(&Bs[nb][bk][bn + 4]) = vb1;
        } else {
#pragma unroll
            for (int j = 0; j < 8; j++) Bs[nb][bk][bn + j] = sb[j];
        }
        __syncthreads();
        bb = nb;
    }

#pragma unroll
    for (int i = 0; i < 4; i++) {
        int gm = m0 + ty * 4 + i;
#pragma unroll
        for (int j = 0; j < 8; j++) {
            int gn = n0 + ((j < 4) ? tx * 4 + j : 64 + tx * 4 + (j - 4));
            if (gn >= N) continue;
            float v = acc[i][j];
            if (DIRECT) {
                v += bias[gn];
                if (RELU) v = fmaxf(v, 0.f);
                Cc[(long)gm * ldc + gn] = v;
            } else {
                Cc[((long)blockIdx.z * M + gm) * (long)N + gn] = v;
            }
        }
    }
}

// ---------------- split-K reduce ----------------
__global__ void reduce_k(const float* __restrict__ part, const float* __restrict__ bias,
                         float* __restrict__ C, int M, int N, int S, int ldc, int relu)
{
    int idx = blockIdx.x * 256 + threadIdx.x;
    if (idx >= M * N) return;
    int m = idx / N, n = idx - m * N;
    float v = 0.f;
    for (int s = 0; s < S; s++) v += part[(long)s * M * N + idx];
    v += bias[n];
    if (relu) v = fmaxf(v, 0.f);
    C[(long)m * ldc + n] = v;
}

// ---------------- depthwise 3x3 conv (padded smem, no bounds checks) ----------------
__global__ void dwconv_k(const float* __restrict__ rf, const float* __restrict__ dwf,
                         const int* __restrict__ im_inds, float* __restrict__ dw)
{
    int n = blockIdx.x, c = blockIdx.y;
    __shared__ float plane[40 * 40];
    __shared__ float f[9];
    int im = im_inds[n];
    const float* src = rf + ((long)im * CD + c) * HW;
    for (int i = threadIdx.x; i < 1600; i += 256) plane[i] = 0.f;
    if (threadIdx.x < 9) f[threadIdx.x] = dwf[((long)n * CD + c) * 9 + threadIdx.x];
    __syncthreads();
    for (int i = threadIdx.x; i < HW; i += 256) {
        int y = i / WF, x = i - y * WF;
        plane[(y + 1) * 40 + x + 1] = src[i];
    }
    __syncthreads();
    float* dst = dw + ((long)n * CD + c) * HW;
    for (int p = threadIdx.x; p < HW; p += 256) {
        int y = p / WF, x = p - y * WF;
        const float* b = &plane[y * 40 + x];
        float s = b[0]  * f[0] + b[1]  * f[1] + b[2]  * f[2]
                + b[40] * f[3] + b[41] * f[4] + b[42] * f[5]
                + b[80] * f[6] + b[81] * f[7] + b[82] * f[8];
        dst[p] = s;
    }
}

// ---------------- dw BN stats ----------------
__global__ void dwstats_k(const float* __restrict__ dw, const float* __restrict__ scale,
                          const float* __restrict__ bias, float* __restrict__ inv,
                          float* __restrict__ sh)
{
    int c = blockIdx.x;
    double s = 0.0, q = 0.0;
    for (int n = 0; n < NOBJ; n++) {
        const float* row = dw + ((long)n * CD + c) * HW;
        for (int p = threadIdx.x; p < HW; p += 256) {
            float v = row[p];
            s += v; q += (double)v * v;
        }
    }
    __shared__ double rs[256], rq[256];
    rs[threadIdx.x] = s; rq[threadIdx.x] = q;
    __syncthreads();
    for (int o = 128; o > 0; o >>= 1) {
        if (threadIdx.x < o) { rs[threadIdx.x] += rs[threadIdx.x + o]; rq[threadIdx.x] += rq[threadIdx.x + o]; }
        __syncthreads();
    }
    if (threadIdx.x == 0) {
        double cnt = (double)ROWS_PW;
        double m = rs[0] / cnt;
        double var = rq[0] / cnt - m * m;
        float iv = scale[c] * (float)(1.0 / sqrt(var + 1e-5));
        inv[c] = iv;
        sh[c]  = bias[c] - (float)m * iv;
    }
}

// ---------------- pw BN stats ----------------
__global__ void pwpart_k(const float* __restrict__ pw, float* __restrict__ pS, float* __restrict__ pQ)
{
    int blk = blockIdx.x;
    int t = threadIdx.x;
    float s0 = 0, q0 = 0, s1 = 0, q1 = 0;
    int r0 = blk * PW_ROWS_PER;
    int r1 = min(ROWS_PW, r0 + PW_ROWS_PER);
    for (int r = r0; r < r1; r++) {
        const float* row = pw + (long)r * CD;
        float v0 = row[t], v1 = row[t + 256];
        s0 += v0; q0 += v0 * v0;
        s1 += v1; q1 += v1 * v1;
    }
    pS[(long)blk * CD + t] = s0;       pS[(long)blk * CD + t + 256] = s1;
    pQ[(long)blk * CD + t] = q0;       pQ[(long)blk * CD + t + 256] = q1;
}

__global__ void pwfin_k(const float* __restrict__ pS, const float* __restrict__ pQ,
                        const float* __restrict__ scale, const float* __restrict__ bias,
                        float* __restrict__ inv, float* __restrict__ sh)
{
    int d = blockIdx.x;
    double s = 0.0, q = 0.0;
    for (int b = threadIdx.x; b < PW_PART_BLOCKS; b += 256) {
        s += pS[(long)b * CD + d];
        q += pQ[(long)b * CD + d];
    }
    __shared__ double rs[256], rq[256];
    rs[threadIdx.x] = s; rq[threadIdx.x] = q;
    __syncthreads();
    for (int o = 128; o > 0; o >>= 1) {
        if (threadIdx.x < o) { rs[threadIdx.x] += rs[threadIdx.x + o]; rq[threadIdx.x] += rq[threadIdx.x + o]; }
        __syncthreads();
    }
    if (threadIdx.x == 0) {
        double cnt = (double)ROWS_PW;
        double m = rs[0] / cnt;
        double var = rq[0] / cnt - m * m;
        float iv = scale[d] * (float)(1.0 / sqrt(var + 1e-5));
        inv[d] = iv;
        sh[d]  = bias[d] - (float)m * iv;
    }
}

// ---------------- ROI-align 7x7 with fused BN+ReLU ----------------
__global__ void roi_k(const float* __restrict__ pw, const float* __restrict__ boxes,
                      const int* __restrict__ rel_inds, const float* __restrict__ inv,
                      const float* __restrict__ sh, float* __restrict__ SO)
{
    int b = blockIdx.x;
    int r = b >> 1, role = b & 1;
    int obj = rel_inds[r * 2 + role];

    __shared__ int yi0[7], yi1[7], xi0[7], xi1[7];
    __shared__ float wy[7], wx[7];
    if (threadIdx.x < 14) {
        int i = threadIdx.x % 7;
        bool isY = threadIdx.x < 7;
        float lo = boxes[obj * 4 + (isY ? 1 : 0)] * (1.0f / 16.0f);
        float hi = boxes[obj * 4 + (isY ? 3 : 2)] * (1.0f / 16.0f);
        float g = ((float)i + 0.5f) / 7.0f;
        float v = lo + (hi - lo) * g;
        float f0 = floorf(v);
        float w = v - f0;
        int i0 = min(max((int)f0, 0), HF - 1);
        int i1 = min(i0 + 1, HF - 1);
        if (isY) { yi0[i] = i0; yi1[i] = i1; wy[i] = w; }
        else     { xi0[i] = i0; xi1[i] = i1; wx[i] = w; }
    }
    __syncthreads();

    const float* base = pw + (long)obj * HW * CD;
    float* dst = SO + (long)r * NPIX * 1024 + role * CD;

    for (int e = threadIdx.x; e < NPIX * CD; e += 256) {
        int pix = e >> 9;
        int c = e & 511;
        int iy = pix / 7, ix = pix - iy * 7;
        int y0 = yi0[iy], y1 = yi1[iy], x0 = xi0[ix], x1 = xi1[ix];
        float fy = wy[iy], fx = wx[ix];
        float ivv = inv[c], shv = sh[c];
        float v00 = fmaxf(base[(long)(y0 * WF + x0) * CD + c] * ivv + shv, 0.f);
        float v01 = fmaxf(base[(long)(y0 * WF + x1) * CD + c] * ivv + shv, 0.f);
        float v10 = fmaxf(base[(long)(y1 * WF + x0) * CD + c] * ivv + shv, 0.f);
        float v11 = fmaxf(base[(long)(y1 * WF + x1) * CD + c] * ivv + shv, 0.f);
        float out = v00 * (1.f - fy) * (1.f - fx) + v01 * (1.f - fy) * fx
                  + v10 * fy * (1.f - fx)         + v11 * fy * fx;
        dst[(long)pix * 1024 + c] = out;
    }
}

// ---------------- concat / triple ----------------
__global__ void cat_k(const float* __restrict__ sub, const int* __restrict__ rel_inds,
                      float* __restrict__ cat)
{
    int idx = blockIdx.x * 256 + threadIdx.x;
    if (idx >= NREL * 1024) return;
    int r = idx >> 10;
    int c = idx & 1023;
    int obj = rel_inds[r * 2 + (c < 512 ? 0 : 1)];
    cat[idx] = sub[(long)obj * 1024 + c];
}

__global__ void triple_k(const float* __restrict__ lo, const float* __restrict__ lr,
                         float* __restrict__ t)
{
    int idx = blockIdx.x * 256 + threadIdx.x;
    if (idx >= NREL * MAPN) return;
    float a = lo[idx], b = lr[idx];
    float d = a - b;
    t[idx] = fmaxf(a + b, 0.f) - d * d;
}

// ---------------- host ----------------
extern "C" void kernel_launch(void* const* d_in, const int* in_sizes, int n_in,
                              void* d_out, int out_size)
{
    (void)in_sizes; (void)n_in; (void)out_size;
    const float* fmaps     = (const float*)d_in[0];
    const float* boxes     = (const float*)d_in[1];
    const float* rof       = (const float*)d_in[2];
    const float* reduce_w  = (const float*)d_in[3];
    const float* reduce_b  = (const float*)d_in[4];
    const float* dw_gen_w  = (const float*)d_in[5];
    const float* dw_gen_b  = (const float*)d_in[6];
    const float* pw_gen_w  = (const float*)d_in[7];
    const float* pw_gen_b  = (const float*)d_in[8];
    const float* dw_bns    = (const float*)d_in[9];
    const float* dw_bnb    = (const float*)d_in[10];
    const float* pw_bns    = (const float*)d_in[11];
    const float* pw_bnb    = (const float*)d_in[12];
    const float* recover_w = (const float*)d_in[13];
    const float* recover_b = (const float*)d_in[14];
    const float* fc1_w     = (const float*)d_in[15];
    const float* fc1_b     = (const float*)d_in[16];
    const float* fc2_w     = (const float*)d_in[17];
    const float* fc2_b     = (const float*)d_in[18];
    const float* post_w    = (const float*)d_in[19];
    const float* post_b    = (const float*)d_in[20];
    const float* map_w     = (const float*)d_in[21];
    const float* map_b     = (const float*)d_in[22];
    const float* rr_w      = (const float*)d_in[23];
    const float* rr_b      = (const float*)d_in[24];
    const float* comp_w    = (const float*)d_in[25];
    const float* comp_b    = (const float*)d_in[26];
    const int*   im_inds   = (const int*)d_in[27];
    const int*   rel_inds  = (const int*)d_in[28];
    float* out = (float*)d_out;

    float *p_dwf, *p_pwf, *p_rf, *p_dw, *p_pw, *p_dwinv, *p_dwsh, *p_pS, *p_pQ,
          *p_pwinv, *p_pwsh, *p_SO, *p_flat, *p_h1, *p_rel, *p_sub, *p_cat,
          *p_lo, *p_lr, *p_t, *p_part;
    cudaGetSymbolAddress((void**)&p_dwf, g_dwf);
    cudaGetSymbolAddress((void**)&p_pwf, g_pwf);
    cudaGetSymbolAddress((void**)&p_rf, g_rf);
    cudaGetSymbolAddress((void**)&p_dw, g_dw);
    cudaGetSymbolAddress((void**)&p_pw, g_pw);
    cudaGetSymbolAddress((void**)&p_dwinv, g_dwinv);
    cudaGetSymbolAddress((void**)&p_dwsh, g_dwsh);
    cudaGetSymbolAddress((void**)&p_pS, g_partS);
    cudaGetSymbolAddress((void**)&p_pQ, g_partQ);
    cudaGetSymbolAddress((void**)&p_pwinv, g_pwinv);
    cudaGetSymbolAddress((void**)&p_pwsh, g_pwsh);
    cudaGetSymbolAddress((void**)&p_SO, g_SO);
    cudaGetSymbolAddress((void**)&p_flat, g_flat);
    cudaGetSymbolAddress((void**)&p_h1, g_h1);
    cudaGetSymbolAddress((void**)&p_rel, g_rel);
    cudaGetSymbolAddress((void**)&p_sub, g_sub);
    cudaGetSymbolAddress((void**)&p_cat, g_cat);
    cudaGetSymbolAddress((void**)&p_lo, g_lo);
    cudaGetSymbolAddress((void**)&p_lr, g_lr);
    cudaGetSymbolAddress((void**)&p_t, g_t);
    cudaGetSymbolAddress((void**)&p_part, g_part);

    // stream-disjoint scratch for the side chain (null-stream users stay < 8.4M floats)
    float* p_part_sub = p_part + (long)12 * 1024 * 1024;  // subobj partials (0.53M)
    float* p_part_map = p_part + (long)13 * 1024 * 1024;  // mapping partials (3.1M)

    // lazily-created side streams + events (graph fork/join pattern; the
    // captured graph is identical on every call -> deterministic work)
    static cudaStream_t s1 = nullptr, s2 = nullptr;
    static cudaEvent_t evRoot = nullptr, evJ1 = nullptr, evJ2 = nullptr;
    if (s1 == nullptr) {
        cudaStreamCreateWithFlags(&s1, cudaStreamNonBlocking);
        cudaStreamCreateWithFlags(&s2, cudaStreamNonBlocking);
        cudaEventCreateWithFlags(&evRoot, cudaEventDisableTiming);
        cudaEventCreateWithFlags(&evJ1, cudaEventDisableTiming);
        cudaEventCreateWithFlags(&evJ2, cudaEventDisableTiming);
    }

    auto T_pwf = tgemm<0,1,false,1,false,false,false>;
    auto T_rf  = tgemm<1,1,false,2,true ,false,false>;
    auto T_pwe = tgemm<1,0,true ,0,false,false,false>;
    auto T_rec = tgemm<0,1,false,1,false,true ,false>;
    auto T_sk  = tgemm<0,1,false,0,false,false,true >;
    cudaFuncSetAttribute(T_pwf, cudaFuncAttributeMaxDynamicSharedMemorySize, TG_SMEM);
    cudaFuncSetAttribute(T_rf , cudaFuncAttributeMaxDynamicSharedMemorySize, TG_SMEM);
    cudaFuncSetAttribute(T_pwe, cudaFuncAttributeMaxDynamicSharedMemorySize, TG_SMEM);
    cudaFuncSetAttribute(T_rec, cudaFuncAttributeMaxDynamicSharedMemorySize, TG_SMEM);
    cudaFuncSetAttribute(T_sk , cudaFuncAttributeMaxDynamicSharedMemorySize, TG_SMEM);

    // ---- fork side streams from the capture (null) stream ----
    cudaEventRecord(evRoot, 0);
    cudaStreamWaitEvent(s1, evRoot, 0);
    cudaStreamWaitEvent(s2, evRoot, 0);

    // ---- s1: pw_f = rof @ pw_gen_w + b (big weight stream, independent) ----
    T_pwf<<<dim3(2048,1,1),512,TG_SMEM,s1>>>(
        rof, pw_gen_w, pw_gen_b, p_pwf, 64,262144,512,0, 512,262144,262144,
        0,0,0, nullptr,nullptr);
    cudaEventRecord(evJ1, s1);

    // ---- s2: subobj -> cat -> mapping (needs only rof; consumed at triple) ----
    gemm_sk<true,false,false><<<dim3(8,1,8),256,0,s2>>>(
        rof, post_w, nullptr, p_part_sub, 64,1024,64, 512,1024,0);
    reduce_k<<<(64*1024+255)/256,256,0,s2>>>(p_part_sub, post_b, p_sub, 64,1024,8,1024,0);
    cat_k<<<(NREL*1024+255)/256,256,0,s2>>>(p_sub, rel_inds, p_cat);
    T_sk<<<dim3(12,2,8),512,TG_SMEM,s2>>>(
        p_cat, map_w, nullptr, p_part_map, NREL,MAPN,1024,128, 1024,MAPN,0,
        0,0,0, nullptr,nullptr);
    reduce_k<<<(NREL*MAPN+255)/256,256,0,s2>>>(p_part_map, map_b, p_lo, NREL,MAPN,8,MAPN,0);
    cudaEventRecord(evJ2, s2);

    // ---- null stream: dw_f, rf, dwconv, dwstats (independent of pwf) ----
    gemm_sk<true,false,false><<<dim3(36,1,4),256>>>(
        rof, dw_gen_w, nullptr, p_part, 64,4608,128, 512,4608,0);
    reduce_k<<<(64*4608+255)/256,256>>>(p_part, dw_gen_b, p_dwf, 64,4608,4,4608,0);

    T_rf<<<dim3(12,4,2),512,TG_SMEM>>>(
        reduce_w, fmaps, reduce_b, p_rf, CD,HW,CD,0, CD,HW,HW,
        0, (long)CD*HW, (long)CD*HW, nullptr,nullptr);

    dwconv_k<<<dim3(NOBJ,CD),256>>>(p_rf, p_dwf, im_inds, p_dw);
    dwstats_k<<<CD,256>>>(p_dw, dw_bns, dw_bnb, p_dwinv, p_dwsh);

    // ---- join s1: pwe needs pwf + dw + dwstats ----
    cudaStreamWaitEvent(0, evJ1, 0);
    T_pwe<<<dim3(4,12,64),512,TG_SMEM>>>(
        p_dw, p_pwf, nullptr, p_pw, HW,CD,CD,0, HW,CD,CD,
        (long)CD*HW, (long)CD*CD, (long)HW*CD, p_dwinv, p_dwsh);

    pwpart_k<<<PW_PART_BLOCKS,256>>>(p_pw, p_pS, p_pQ);
    pwfin_k<<<CD,256>>>(p_pS, p_pQ, pw_bns, pw_bnb, p_pwinv, p_pwsh);

    roi_k<<<NREL*2,256>>>(p_pw, boxes, rel_inds, p_pwinv, p_pwsh, p_SO);

    T_rec<<<dim3(4,98,1),512,TG_SMEM>>>(
        p_SO, recover_w, recover_b, p_flat, NREL*NPIX,CD,1024,0, 1024,CD,0,
        0,0,0, nullptr,nullptr);

    // fc1 (split-K S=8, kc=3136)
    T_sk<<<dim3(32,2,8),512,TG_SMEM>>>(
        p_flat, fc1_w, nullptr, p_part, NREL,FCH,FC1K,3136, FC1K,FCH,0,
        0,0,0, nullptr,nullptr);
    reduce_k<<<(NREL*FCH+255)/256,256>>>(p_part, fc1_b, p_h1, NREL,FCH,8,FCH,1);

    // fc2 (split-K S=8, kc=512)
    T_sk<<<dim3(32,2,8),512,TG_SMEM>>>(
        p_h1, fc2_w, nullptr, p_part, NREL,FCH,FCH,512, FCH,FCH,0,
        0,0,0, nullptr,nullptr);
    reduce_k<<<(NREL*FCH+255)/256,256>>>(p_part, fc2_b, p_rel, NREL,FCH,8,FCH,0);

    // last_rel (split-K S=16, kc=256)
    T_sk<<<dim3(12,2,16),512,TG_SMEM>>>(
        p_rel, rr_w, nullptr, p_part, NREL,MAPN,FCH,256, FCH,MAPN,0,
        0,0,0, nullptr,nullptr);
    reduce_k<<<(NREL*MAPN+255)/256,256>>>(p_part, rr_b, p_lr, NREL,MAPN,16,MAPN,0);

    // ---- join s2: triple needs lo ----
    cudaStreamWaitEvent(0, evJ2, 0);
    triple_k<<<(NREL*MAPN+255)/256,256>>>(p_lo, p_lr, p_t);

    // comp (fp32, N=51, split-K S=8)
    gemm_k<true><<<dim3(1,2,8),256>>>(
        p_t, comp_w, p_part, NREL,OUTN,MAPN,192, MAPN,OUTN);
    reduce_k<<<(NREL*OUTN+255)/256,256>>>(p_part, comp_b, out, NREL,OUTN,8,OUTN,0);
}